// round 2
// baseline (speedup 1.0000x reference)
#include <cuda_runtime.h>

#define DI __device__ __forceinline__

// Problem dims (fixed by the dataset)
// B=512, T=128, D=300, H=64; M = B*T = 65536 rows per input; NC = 192 fused cols (u|g|a)

// ---------------- scratch (device globals; no allocations allowed) ----------------
__device__ float  g_pre[2u * 65536u * 192u];   // [input][b*128+t][192]  (~100.7 MB)
__device__ float  g_Wcat[300 * 192];           // [k][c] c<64:Wu, <128:Wg_x, <192:Wa_x
__device__ float  g_bias[192];                 // bu | bg | 0
__device__ float2 g_hW2[64 * 64];              // [k][j] = {Wg[300+k][j], Wa[300+k][j]}
__device__ float  g_hn[512 * 128];             // concat(hn1, hn2) per batch row
__device__ float  g_bnm[128];
__device__ float  g_bnr[128];

// ---------------- f32x2 helpers ----------------
DI unsigned long long f32x2_fma(unsigned long long a, unsigned long long b, unsigned long long c) {
    unsigned long long d;
    asm("fma.rn.f32x2 %0, %1, %2, %3;" : "=l"(d) : "l"(a), "l"(b), "l"(c));
    return d;
}
DI unsigned long long pack2(float x, float y) {
    unsigned long long r;
    asm("mov.b64 %0, {%1, %2};" : "=l"(r) : "f"(x), "f"(y));
    return r;
}
DI float2 unpack2(unsigned long long v) {
    float2 f;
    asm("mov.b64 {%0, %1}, %2;" : "=f"(f.x), "=f"(f.y) : "l"(v));
    return f;
}

// ---------------- weight packing ----------------
__global__ void pack_kernel(const float* __restrict__ Wu, const float* __restrict__ bu,
                            const float* __restrict__ Wg, const float* __restrict__ bg,
                            const float* __restrict__ Wa) {
    int i = blockIdx.x * blockDim.x + threadIdx.x;
    if (i < 300 * 192) {
        int k = i / 192, c = i % 192;
        float v;
        if (c < 64)       v = Wu[k * 64 + c];
        else if (c < 128) v = Wg[k * 64 + (c - 64)];
        else              v = Wa[k * 64 + (c - 128)];
        g_Wcat[i] = v;
    }
    if (i < 192) {
        g_bias[i] = (i < 64) ? bu[i] : (i < 128 ? bg[i - 64] : 0.f);
    }
    if (i < 64 * 64) {
        int k = i / 64, j = i % 64;
        g_hW2[i] = make_float2(Wg[(300 + k) * 64 + j], Wa[(300 + k) * 64 + j]);
    }
}

// ---------------- fused input GEMM: pre = x @ Wcat + bias ----------------
// BM=128, BN=64, BK=16, 256 threads, per-thread 8x4 micro-tile via f32x2 FMA
__global__ void __launch_bounds__(256) gemm_kernel(const float* __restrict__ x1,
                                                   const float* __restrict__ x2) {
    const int mblk = blockIdx.x;   // 0..511
    const int nblk = blockIdx.y;   // 0..2
    const int inp  = blockIdx.z;   // 0..1
    const float* __restrict__ X = inp ? x2 : x1;
    float* __restrict__ out = g_pre + (size_t)inp * 65536u * 192u;

    __shared__ float As[16][132];  // padded: 132%4==0 keeps float4 align, breaks bank cycles
    __shared__ float Bs[16][64];

    const int tid = threadIdx.x;
    const int tx = tid & 15, ty = tid >> 4;
    const int m0 = mblk * 128;
    const int n0 = nblk * 64;

    unsigned long long acc[8][2];
#pragma unroll
    for (int i = 0; i < 8; i++) { acc[i][0] = 0ull; acc[i][1] = 0ull; }

    const int la_row = tid >> 2;         // 0..63
    const int la_k4  = (tid & 3) * 4;    // 0,4,8,12
    const int lb_k   = tid >> 4;         // 0..15
    const int lb_c4  = (tid & 15) * 4;

    for (int k0 = 0; k0 < 300; k0 += 16) {
#pragma unroll
        for (int rr = 0; rr < 2; rr++) {
            int m = la_row + rr * 64;
            float4 v = make_float4(0.f, 0.f, 0.f, 0.f);
            if (k0 + la_k4 < 300)  // 300 % 4 == 0 -> whole float4 valid or none
                v = *(const float4*)&X[(size_t)(m0 + m) * 300 + k0 + la_k4];
            As[la_k4 + 0][m] = v.x;
            As[la_k4 + 1][m] = v.y;
            As[la_k4 + 2][m] = v.z;
            As[la_k4 + 3][m] = v.w;
        }
        {
            float4 v = make_float4(0.f, 0.f, 0.f, 0.f);
            if (k0 + lb_k < 300)
                v = *(const float4*)&g_Wcat[(size_t)(k0 + lb_k) * 192 + n0 + lb_c4];
            *(float4*)&Bs[lb_k][lb_c4] = v;
        }
        __syncthreads();
#pragma unroll
        for (int k = 0; k < 16; k++) {
            float4 b4 = *(const float4*)&Bs[k][tx * 4];
            unsigned long long b01 = pack2(b4.x, b4.y);
            unsigned long long b23 = pack2(b4.z, b4.w);
            float4 a0 = *(const float4*)&As[k][ty * 8];
            float4 a1 = *(const float4*)&As[k][ty * 8 + 4];
            float av[8] = {a0.x, a0.y, a0.z, a0.w, a1.x, a1.y, a1.z, a1.w};
#pragma unroll
            for (int i = 0; i < 8; i++) {
                unsigned long long aa = pack2(av[i], av[i]);
                acc[i][0] = f32x2_fma(aa, b01, acc[i][0]);
                acc[i][1] = f32x2_fma(aa, b23, acc[i][1]);
            }
        }
        __syncthreads();
    }

    float4 bias = *(const float4*)&g_bias[n0 + tx * 4];
#pragma unroll
    for (int i = 0; i < 8; i++) {
        float2 c01 = unpack2(acc[i][0]);
        float2 c23 = unpack2(acc[i][1]);
        float4 v = make_float4(c01.x + bias.x, c01.y + bias.y, c23.x + bias.z, c23.y + bias.w);
        *(float4*)&out[(size_t)(m0 + ty * 8 + i) * 192 + n0 + tx * 4] = v;
    }
}

// ---------------- sequential recurrence ----------------
// 1024 sequences (2 inputs x 512 batch). Block = 256 threads = 64 hidden x 4 groups,
// each thread carries 2 sequences -> 8 sequences/block, 128 blocks.
__global__ void __launch_bounds__(256) recur_kernel(const float* __restrict__ s) {
    __shared__ float2 W2s[64 * 64];     // 32 KB: [k][j] = {wg, wa}
    __shared__ float  hbuf[2][64][10];  // [buf][k][local_seq(8), padded]

    const int tid = threadIdx.x;
    const int j = tid & 63, grp = tid >> 6;

    for (int i = tid; i < 4096; i += 256) W2s[i] = g_hW2[i];

    const int ls0 = grp * 2, ls1 = ls0 + 1;
    const int sidx0 = blockIdx.x * 8 + ls0;
    const int sidx1 = sidx0 + 1;
    const float* __restrict__ pre0 = g_pre + (size_t)sidx0 * 128u * 192u;
    const float* __restrict__ pre1 = g_pre + (size_t)sidx1 * 128u * 192u;

    const float h0 = tanhf(s[j]);
    float n0 = 0.f, dd0 = 0.f, am0 = -1e38f, hf0 = h0;
    float n1 = 0.f, dd1 = 0.f, am1 = -1e38f, hf1 = h0;

    hbuf[0][j][ls0] = h0;
    hbuf[0][j][ls1] = h0;
    __syncthreads();
    int p = 0;

    float u0 = pre0[j], gg0 = pre0[64 + j], aa0 = pre0[128 + j];
    float u1 = pre1[j], gg1 = pre1[64 + j], aa1 = pre1[128 + j];

    for (int t = 0; t < 128; t++) {
        float nu0 = 0.f, ng0 = 0.f, na0 = 0.f, nu1 = 0.f, ng1 = 0.f, na1 = 0.f;
        if (t < 127) {  // prefetch next step's (u,g,a)
            const float* q0 = pre0 + (size_t)(t + 1) * 192;
            const float* q1 = pre1 + (size_t)(t + 1) * 192;
            nu0 = q0[j]; ng0 = q0[64 + j]; na0 = q0[128 + j];
            nu1 = q1[j]; ng1 = q1[64 + j]; na1 = q1[128 + j];
        }

        unsigned long long acc0 = pack2(gg0, aa0);
        unsigned long long acc1 = pack2(gg1, aa1);
#pragma unroll
        for (int k = 0; k < 64; k++) {
            unsigned long long w = *(const unsigned long long*)&W2s[k * 64 + j];
            float2 hh = *(const float2*)&hbuf[p][k][ls0];
            acc0 = f32x2_fma(pack2(hh.x, hh.x), w, acc0);
            acc1 = f32x2_fma(pack2(hh.y, hh.y), w, acc1);
        }
        float2 ga0 = unpack2(acc0), ga1 = unpack2(acc1);

        {
            float z  = u0 * tanhf(ga0.x);
            float an = fmaxf(am0, ga0.y);
            float eo = __expf(am0 - an);
            float ea = __expf(ga0.y - an);
            n0  = n0 * eo + z * ea;
            dd0 = dd0 * eo + ea;
            am0 = an;
            hf0 = tanhf(n0 / dd0);
            hbuf[p ^ 1][j][ls0] = hf0;
        }
        {
            float z  = u1 * tanhf(ga1.x);
            float an = fmaxf(am1, ga1.y);
            float eo = __expf(am1 - an);
            float ea = __expf(ga1.y - an);
            n1  = n1 * eo + z * ea;
            dd1 = dd1 * eo + ea;
            am1 = an;
            hf1 = tanhf(n1 / dd1);
            hbuf[p ^ 1][j][ls1] = hf1;
        }
        __syncthreads();
        p ^= 1;
        u0 = nu0; gg0 = ng0; aa0 = na0;
        u1 = nu1; gg1 = ng1; aa1 = na1;
    }

    {
        int inp = sidx0 >> 9, b = sidx0 & 511;
        g_hn[b * 128 + inp * 64 + j] = hf0;
    }
    {
        int inp = sidx1 >> 9, b = sidx1 & 511;
        g_hn[b * 128 + inp * 64 + j] = hf1;
    }
}

// ---------------- batchnorm stats (training-mode batch stats, gamma=1, beta=0) ----------------
__global__ void bnstats_kernel() {
    const int c = blockIdx.x;       // 0..127
    const int tid = threadIdx.x;    // 256
    float s = 0.f, sq = 0.f;
#pragma unroll
    for (int r = tid; r < 512; r += 256) {
        float v = g_hn[r * 128 + c];
        s += v; sq += v * v;
    }
#pragma unroll
    for (int o = 16; o; o >>= 1) {
        s  += __shfl_down_sync(0xffffffffu, s, o);
        sq += __shfl_down_sync(0xffffffffu, sq, o);
    }
    __shared__ float ss[8], qs[8];
    if ((tid & 31) == 0) { ss[tid >> 5] = s; qs[tid >> 5] = sq; }
    __syncthreads();
    if (tid == 0) {
        float S = 0.f, Q = 0.f;
#pragma unroll
        for (int w = 0; w < 8; w++) { S += ss[w]; Q += qs[w]; }
        float mean = S * (1.f / 512.f);
        float var  = Q * (1.f / 512.f) - mean * mean;
        g_bnm[c] = mean;
        g_bnr[c] = rsqrtf(var + 1e-5f);
    }
}

// ---------------- head: BN -> W1 -> PReLU -> W2 -> sigmoid ----------------
__global__ void head_kernel(const float* __restrict__ W1, const float* __restrict__ b1,
                            const float* __restrict__ pw, const float* __restrict__ W2,
                            const float* __restrict__ b2, float* __restrict__ out) {
    const int r = blockIdx.x;     // 0..511
    const int t = threadIdx.x;    // 0..63
    __shared__ float xs[128];
    for (int k = t; k < 128; k += 64)
        xs[k] = (g_hn[r * 128 + k] - g_bnm[k]) * g_bnr[k];
    __syncthreads();

    float acc = b1[t];
#pragma unroll
    for (int k = 0; k < 128; k++)
        acc = fmaf(xs[k], W1[k * 64 + t], acc);
    float pwv = *pw;
    acc = (acc >= 0.f) ? acc : pwv * acc;
    float v = acc * W2[t];
#pragma unroll
    for (int o = 16; o; o >>= 1) v += __shfl_down_sync(0xffffffffu, v, o);
    __shared__ float red[2];
    if ((t & 31) == 0) red[t >> 5] = v;
    __syncthreads();
    if (t == 0) {
        float sum = red[0] + red[1] + b2[0];
        out[r] = 1.f / (1.f + __expf(-sum));
    }
}

// ---------------- launch ----------------
extern "C" void kernel_launch(void* const* d_in, const int* in_sizes, int n_in,
                              void* d_out, int out_size) {
    const float* in1 = (const float*)d_in[0];
    const float* in2 = (const float*)d_in[1];
    const float* Wu  = (const float*)d_in[2];
    const float* bu  = (const float*)d_in[3];
    const float* Wg  = (const float*)d_in[4];
    const float* bg  = (const float*)d_in[5];
    const float* Wa  = (const float*)d_in[6];
    const float* s   = (const float*)d_in[7];
    const float* W1  = (const float*)d_in[8];
    const float* b1  = (const float*)d_in[9];
    const float* pw  = (const float*)d_in[10];
    const float* W2  = (const float*)d_in[11];
    const float* b2  = (const float*)d_in[12];
    float* out = (float*)d_out;

    pack_kernel<<<226, 256>>>(Wu, bu, Wg, bg, Wa);
    gemm_kernel<<<dim3(512, 3, 2), 256>>>(in1, in2);
    recur_kernel<<<128, 256>>>(s);
    bnstats_kernel<<<128, 256>>>();
    head_kernel<<<512, 64>>>(W1, b1, pw, W2, b2, out);
}

// round 6
// speedup vs baseline: 1.1913x; 1.1913x over previous
#include <cuda_runtime.h>
#include <cuda_bf16.h>

#define DI __device__ __forceinline__
typedef unsigned int u32;
typedef unsigned long long u64;

// Problem dims: B=512, T=128, D=300, H=64. M=65536 rows/input, 192 fused cols (u|g|a).
// GEMM kernel: CTA = 128 rows x 64 cols, K padded 300->304 (19 k16 steps), mma.sync bf16
// with hi/lo split (3 products) for fp32-level accuracy.

// ---------------- device-global scratch ----------------
__device__ float          g_pre[2u * 65536u * 192u];   // [input][row][192]
__device__ unsigned short g_WtH[192 * 304];            // W^T hi bf16 [n][k], zero-padded k>=300
__device__ unsigned short g_WtL[192 * 304];            // W^T lo bf16
__device__ float          g_bias[192];                 // bu | bg | 0
__device__ float2         g_hW2[64 * 64];              // [k][j] = {Wg_h, Wa_h}
__device__ float          g_hn[512 * 128];
__device__ float          g_bnm[128];
__device__ float          g_bnr[128];

// ---------------- helpers ----------------
DI u64 f32x2_fma(u64 a, u64 b, u64 c) {
    u64 d;
    asm("fma.rn.f32x2 %0, %1, %2, %3;" : "=l"(d) : "l"(a), "l"(b), "l"(c));
    return d;
}
DI u64 pack2(float x, float y) {
    u64 r;
    asm("mov.b64 %0, {%1, %2};" : "=l"(r) : "f"(x), "f"(y));
    return r;
}
DI float2 unpack2(u64 v) {
    float2 f;
    asm("mov.b64 {%0, %1}, %2;" : "=f"(f.x), "=f"(f.y) : "l"(v));
    return f;
}
// split two floats into packed-bf16 hi and lo
DI void split2(float a, float b, u32& hi, u32& lo) {
    __nv_bfloat16 ha = __float2bfloat16(a), hb = __float2bfloat16(b);
    __nv_bfloat16 la = __float2bfloat16(a - __bfloat162float(ha));
    __nv_bfloat16 lb = __float2bfloat16(b - __bfloat162float(hb));
    hi = (u32)__bfloat16_as_ushort(ha) | ((u32)__bfloat16_as_ushort(hb) << 16);
    lo = (u32)__bfloat16_as_ushort(la) | ((u32)__bfloat16_as_ushort(lb) << 16);
}
DI void mma16816(float* c, u32 a0, u32 a1, u32 a2, u32 a3, u32 b0, u32 b1) {
    asm volatile(
        "mma.sync.aligned.m16n8k16.row.col.f32.bf16.bf16.f32 "
        "{%0,%1,%2,%3}, {%4,%5,%6,%7}, {%8,%9}, {%0,%1,%2,%3};"
        : "+f"(c[0]), "+f"(c[1]), "+f"(c[2]), "+f"(c[3])
        : "r"(a0), "r"(a1), "r"(a2), "r"(a3), "r"(b0), "r"(b1));
}

// ---------------- weight packing ----------------
__global__ void pack_kernel(const float* __restrict__ Wu, const float* __restrict__ bu,
                            const float* __restrict__ Wg, const float* __restrict__ bg,
                            const float* __restrict__ Wa) {
    int i = blockIdx.x * blockDim.x + threadIdx.x;
    if (i < 192 * 304) {
        int n = i / 304, k = i % 304;
        float v = 0.f;
        if (k < 300) {
            if (n < 64)       v = Wu[k * 64 + n];
            else if (n < 128) v = Wg[k * 64 + (n - 64)];
            else              v = Wa[k * 64 + (n - 128)];
        }
        __nv_bfloat16 h = __float2bfloat16(v);
        g_WtH[i] = __bfloat16_as_ushort(h);
        g_WtL[i] = __bfloat16_as_ushort(__float2bfloat16(v - __bfloat162float(h)));
    }
    if (i < 192) g_bias[i] = (i < 64) ? bu[i] : (i < 128 ? bg[i - 64] : 0.f);
    if (i < 64 * 64) {
        int k = i / 64, j = i % 64;
        g_hW2[i] = make_float2(Wg[(300 + k) * 64 + j], Wa[(300 + k) * 64 + j]);
    }
}

// ---------------- mma.sync split-bf16 GEMM: pre = x @ Wcat + bias ----------------
// grid (3, 512, 2) = (nblk, mblk, inp); 256 threads = 8 warps (4m x 2n), warp tile 32x32.
// smem row stride 24 bf16 (48B = 12 banks) -> conflict-free b32 fragment loads.
#define ASTR 24
__global__ void __launch_bounds__(256) gemm_mma_kernel(const float* __restrict__ x1,
                                                       const float* __restrict__ x2) {
    __shared__ __align__(16) unsigned short AH[2][128 * ASTR];
    __shared__ __align__(16) unsigned short AL[2][128 * ASTR];
    __shared__ __align__(16) unsigned short BH[2][64 * ASTR];
    __shared__ __align__(16) unsigned short BL[2][64 * ASTR];
    __shared__ float bias_s[64];

    const int tid = threadIdx.x, lane = tid & 31, wid = tid >> 5;
    const int warp_m = wid & 3, warp_n = wid >> 2;
    const int nblk = blockIdx.x, mblk = blockIdx.y, inp = blockIdx.z;
    const float* __restrict__ X = inp ? x2 : x1;
    const size_t m0 = (size_t)mblk * 128u;
    const int n0g = nblk * 64;
    float* __restrict__ outp = g_pre + ((size_t)inp * 65536u + m0) * 192u;

    if (tid < 64) bias_s[tid] = g_bias[n0g + tid];

    // loader maps
    const int a_r = tid >> 1, a_s = tid & 1;               // A: row 0..127, k-half 0/1
    const int b_n = (tid & 127) >> 1, b_s = tid & 1;       // B: n 0..63, k-half
    const int b_part = tid >> 7;                           // 0: hi, 1: lo
    const unsigned short* __restrict__ Wsrc = b_part ? g_WtL : g_WtH;

    float c[2][4][4];
#pragma unroll
    for (int i = 0; i < 2; i++)
#pragma unroll
        for (int j = 0; j < 4; j++)
#pragma unroll
            for (int q = 0; q < 4; q++) c[i][j][q] = 0.f;

    // prefetch k-step 0
    float4 av0 = make_float4(0.f, 0.f, 0.f, 0.f), av1 = av0;
    uint4 bv;
    {
        int kg = a_s * 8;
        av0 = *(const float4*)&X[(m0 + a_r) * 300 + kg];
        if (kg + 4 < 300) av1 = *(const float4*)&X[(m0 + a_r) * 300 + kg + 4];
        bv = *(const uint4*)&Wsrc[(n0g + b_n) * 304 + b_s * 8];
    }

    int p = 0;
    for (int ck = 0; ck < 19; ck++) {
        __syncthreads();   // all reads of buffer p (iter ck-2) done
        // ---- store prefetched tile into smem buffer p ----
        {
            u32 h0, l0, h1, l1, h2, l2, h3, l3;
            split2(av0.x, av0.y, h0, l0);
            split2(av0.z, av0.w, h1, l1);
            split2(av1.x, av1.y, h2, l2);
            split2(av1.z, av1.w, h3, l3);
            int off = a_r * ASTR + a_s * 8;
            *(uint4*)&AH[p][off] = make_uint4(h0, h1, h2, h3);
            *(uint4*)&AL[p][off] = make_uint4(l0, l1, l2, l3);
            int boff = b_n * ASTR + b_s * 8;
            if (b_part == 0) *(uint4*)&BH[p][boff] = bv;
            else             *(uint4*)&BL[p][boff] = bv;
        }
        __syncthreads();
        // ---- prefetch next k-step from global ----
        if (ck < 18) {
            int kg = (ck + 1) * 16 + a_s * 8;
            av0 = (kg < 300)     ? *(const float4*)&X[(m0 + a_r) * 300 + kg]
                                 : make_float4(0.f, 0.f, 0.f, 0.f);
            av1 = (kg + 4 < 300) ? *(const float4*)&X[(m0 + a_r) * 300 + kg + 4]
                                 : make_float4(0.f, 0.f, 0.f, 0.f);
            bv = *(const uint4*)&Wsrc[(n0g + b_n) * 304 + (ck + 1) * 16 + b_s * 8];
        }
        // ---- compute from buffer p ----
        u32 ah[2][4], al[2][4];
#pragma unroll
        for (int mf = 0; mf < 2; mf++) {
            int r0 = warp_m * 32 + mf * 16 + (lane >> 2);
            int base = r0 * ASTR + (lane & 3) * 2;
            ah[mf][0] = *(const u32*)&AH[p][base];
            ah[mf][1] = *(const u32*)&AH[p][base + 8 * ASTR];
            ah[mf][2] = *(const u32*)&AH[p][base + 8];
            ah[mf][3] = *(const u32*)&AH[p][base + 8 * ASTR + 8];
            al[mf][0] = *(const u32*)&AL[p][base];
            al[mf][1] = *(const u32*)&AL[p][base + 8 * ASTR];
            al[mf][2] = *(const u32*)&AL[p][base + 8];
            al[mf][3] = *(const u32*)&AL[p][base + 8 * ASTR + 8];
        }
#pragma unroll
        for (int nf = 0; nf < 4; nf++) {
            int nr = warp_n * 32 + nf * 8 + (lane >> 2);
            int base = nr * ASTR + (lane & 3) * 2;
            u32 bh0 = *(const u32*)&BH[p][base];
            u32 bh1 = *(const u32*)&BH[p][base + 8];
            u32 bl0 = *(const u32*)&BL[p][base];
            u32 bl1 = *(const u32*)&BL[p][base + 8];
#pragma unroll
            for (int mf = 0; mf < 2; mf++) {
                mma16816(c[mf][nf], ah[mf][0], ah[mf][1], ah[mf][2], ah[mf][3], bh0, bh1);
                mma16816(c[mf][nf], ah[mf][0], ah[mf][1], ah[mf][2], ah[mf][3], bl0, bl1);
                mma16816(c[mf][nf], al[mf][0], al[mf][1], al[mf][2], al[mf][3], bh0, bh1);
            }
        }
        p ^= 1;
    }

    // ---- epilogue: +bias, write g_pre ----
#pragma unroll
    for (int mf = 0; mf < 2; mf++) {
#pragma unroll
        for (int nf = 0; nf < 4; nf++) {
            int row = warp_m * 32 + mf * 16 + (lane >> 2);
            int col = warp_n * 32 + nf * 8 + 2 * (lane & 3);
            float bx = bias_s[col], by = bias_s[col + 1];
            float2 v0 = make_float2(c[mf][nf][0] + bx, c[mf][nf][1] + by);
            float2 v1 = make_float2(c[mf][nf][2] + bx, c[mf][nf][3] + by);
            *(float2*)&outp[(size_t)row * 192 + n0g + col] = v0;
            *(float2*)&outp[(size_t)(row + 8) * 192 + n0g + col] = v1;
        }
    }
}

// ---------------- sequential recurrence ----------------
__global__ void __launch_bounds__(256) recur_kernel(const float* __restrict__ s) {
    __shared__ float2 W2s[64 * 64];
    __shared__ float  hbuf[2][64][10];

    const int tid = threadIdx.x;
    const int j = tid & 63, grp = tid >> 6;

    for (int i = tid; i < 4096; i += 256) W2s[i] = g_hW2[i];

    const int ls0 = grp * 2, ls1 = ls0 + 1;
    const int sidx0 = blockIdx.x * 8 + ls0;
    const int sidx1 = sidx0 + 1;
    const float* __restrict__ pre0 = g_pre + (size_t)sidx0 * 128u * 192u;
    const float* __restrict__ pre1 = g_pre + (size_t)sidx1 * 128u * 192u;

    const float h0 = tanhf(s[j]);
    float n0 = 0.f, dd0 = 0.f, am0 = -1e38f, hf0 = h0;
    float n1 = 0.f, dd1 = 0.f, am1 = -1e38f, hf1 = h0;

    hbuf[0][j][ls0] = h0;
    hbuf[0][j][ls1] = h0;
    __syncthreads();
    int p = 0;

    float u0 = pre0[j], gg0 = pre0[64 + j], aa0 = pre0[128 + j];
    float u1 = pre1[j], gg1 = pre1[64 + j], aa1 = pre1[128 + j];

    for (int t = 0; t < 128; t++) {
        float nu0 = 0.f, ng0 = 0.f, na0 = 0.f, nu1 = 0.f, ng1 = 0.f, na1 = 0.f;
        if (t < 127) {
            const float* q0 = pre0 + (size_t)(t + 1) * 192;
            const float* q1 = pre1 + (size_t)(t + 1) * 192;
            nu0 = q0[j]; ng0 = q0[64 + j]; na0 = q0[128 + j];
            nu1 = q1[j]; ng1 = q1[64 + j]; na1 = q1[128 + j];
        }

        u64 acc0 = pack2(gg0, aa0);
        u64 acc1 = pack2(gg1, aa1);
#pragma unroll
        for (int k = 0; k < 64; k++) {
            u64 w = *(const u64*)&W2s[k * 64 + j];
            float2 hh = *(const float2*)&hbuf[p][k][ls0];
            acc0 = f32x2_fma(pack2(hh.x, hh.x), w, acc0);
            acc1 = f32x2_fma(pack2(hh.y, hh.y), w, acc1);
        }
        float2 ga0 = unpack2(acc0), ga1 = unpack2(acc1);

        {
            float z  = u0 * tanhf(ga0.x);
            float an = fmaxf(am0, ga0.y);
            float eo = __expf(am0 - an);
            float ea = __expf(ga0.y - an);
            n0  = n0 * eo + z * ea;
            dd0 = dd0 * eo + ea;
            am0 = an;
            hf0 = tanhf(n0 / dd0);
            hbuf[p ^ 1][j][ls0] = hf0;
        }
        {
            float z  = u1 * tanhf(ga1.x);
            float an = fmaxf(am1, ga1.y);
            float eo = __expf(am1 - an);
            float ea = __expf(ga1.y - an);
            n1  = n1 * eo + z * ea;
            dd1 = dd1 * eo + ea;
            am1 = an;
            hf1 = tanhf(n1 / dd1);
            hbuf[p ^ 1][j][ls1] = hf1;
        }
        __syncthreads();
        p ^= 1;
        u0 = nu0; gg0 = ng0; aa0 = na0;
        u1 = nu1; gg1 = ng1; aa1 = na1;
    }

    {
        int inp = sidx0 >> 9, b = sidx0 & 511;
        g_hn[b * 128 + inp * 64 + j] = hf0;
    }
    {
        int inp = sidx1 >> 9, b = sidx1 & 511;
        g_hn[b * 128 + inp * 64 + j] = hf1;
    }
}

// ---------------- batchnorm stats ----------------
__global__ void bnstats_kernel() {
    const int c = blockIdx.x;
    const int tid = threadIdx.x;
    float s = 0.f, sq = 0.f;
#pragma unroll
    for (int r = tid; r < 512; r += 256) {
        float v = g_hn[r * 128 + c];
        s += v; sq += v * v;
    }
#pragma unroll
    for (int o = 16; o; o >>= 1) {
        s  += __shfl_down_sync(0xffffffffu, s, o);
        sq += __shfl_down_sync(0xffffffffu, sq, o);
    }
    __shared__ float ss[8], qs[8];
    if ((tid & 31) == 0) { ss[tid >> 5] = s; qs[tid >> 5] = sq; }
    __syncthreads();
    if (tid == 0) {
        float S = 0.f, Q = 0.f;
#pragma unroll
        for (int w = 0; w < 8; w++) { S += ss[w]; Q += qs[w]; }
        float mean = S * (1.f / 512.f);
        float var  = Q * (1.f / 512.f) - mean * mean;
        g_bnm[c] = mean;
        g_bnr[c] = rsqrtf(var + 1e-5f);
    }
}

// ---------------- head ----------------
__global__ void head_kernel(const float* __restrict__ W1, const float* __restrict__ b1,
                            const float* __restrict__ pw, const float* __restrict__ W2,
                            const float* __restrict__ b2, float* __restrict__ out) {
    const int r = blockIdx.x;
    const int t = threadIdx.x;
    __shared__ float xs[128];
    for (int k = t; k < 128; k += 64)
        xs[k] = (g_hn[r * 128 + k] - g_bnm[k]) * g_bnr[k];
    __syncthreads();

    float acc = b1[t];
#pragma unroll
    for (int k = 0; k < 128; k++)
        acc = fmaf(xs[k], W1[k * 64 + t], acc);
    float pwv = *pw;
    acc = (acc >= 0.f) ? acc : pwv * acc;
    float v = acc * W2[t];
#pragma unroll
    for (int o = 16; o; o >>= 1) v += __shfl_down_sync(0xffffffffu, v, o);
    __shared__ float red[2];
    if ((t & 31) == 0) red[t >> 5] = v;
    __syncthreads();
    if (t == 0) {
        float sum = red[0] + red[1] + b2[0];
        out[r] = 1.f / (1.f + __expf(-sum));
    }
}

// ---------------- launch ----------------
extern "C" void kernel_launch(void* const* d_in, const int* in_sizes, int n_in,
                              void* d_out, int out_size) {
    const float* in1 = (const float*)d_in[0];
    const float* in2 = (const float*)d_in[1];
    const float* Wu  = (const float*)d_in[2];
    const float* bu  = (const float*)d_in[3];
    const float* Wg  = (const float*)d_in[4];
    const float* bg  = (const float*)d_in[5];
    const float* Wa  = (const float*)d_in[6];
    const float* s   = (const float*)d_in[7];
    const float* W1  = (const float*)d_in[8];
    const float* b1  = (const float*)d_in[9];
    const float* pw  = (const float*)d_in[10];
    const float* W2  = (const float*)d_in[11];
    const float* b2  = (const float*)d_in[12];
    float* out = (float*)d_out;

    pack_kernel<<<229, 256>>>(Wu, bu, Wg, bg, Wa);
    gemm_mma_kernel<<<dim3(3, 512, 2), 256>>>(in1, in2);
    recur_kernel<<<128, 256>>>(s);
    bnstats_kernel<<<128, 256>>>();
    head_kernel<<<512, 64>>>(W1, b1, pw, W2, b2, out);
}

// round 8
// speedup vs baseline: 1.3336x; 1.1194x over previous
#include <cuda_runtime.h>
#include <cuda_bf16.h>

#define DI __device__ __forceinline__
typedef unsigned int u32;
typedef unsigned long long u64;

// B=512, T=128, D=300, H=64. M=65536 rows/input, 192 fused cols (u|g|a).
// GEMM: one CTA = 128 rows x 192 cols (full N), K 300->304, 19 k16 steps.
// Split-bf16 (hi/lo, 3 products) mma.sync for fp32-level accuracy.

// ---------------- device-global scratch ----------------
__device__ float          g_pre[2u * 65536u * 192u];   // [input][row][192]
__device__ unsigned short g_WtH[192 * 304];            // W^T hi bf16 [n][k], zero-pad k>=300
__device__ unsigned short g_WtL[192 * 304];            // W^T lo bf16
__device__ float          g_bias[192];                 // bu | bg | 0
__device__ float2         g_hW2[64 * 64];              // [k][j] = {Wg_h, Wa_h}
__device__ float          g_hn[512 * 128];
__device__ float          g_bnm[128];
__device__ float          g_bnr[128];

// ---------------- helpers ----------------
DI u64 f32x2_fma(u64 a, u64 b, u64 c) {
    u64 d;
    asm("fma.rn.f32x2 %0, %1, %2, %3;" : "=l"(d) : "l"(a), "l"(b), "l"(c));
    return d;
}
DI u64 pack2(float x, float y) {
    u64 r;
    asm("mov.b64 %0, {%1, %2};" : "=l"(r) : "f"(x), "f"(y));
    return r;
}
DI float2 unpack2(u64 v) {
    float2 f;
    asm("mov.b64 {%0, %1}, %2;" : "=f"(f.x), "=f"(f.y) : "l"(v));
    return f;
}
DI void split2(float a, float b, u32& hi, u32& lo) {
    __nv_bfloat16 ha = __float2bfloat16(a), hb = __float2bfloat16(b);
    __nv_bfloat16 la = __float2bfloat16(a - __bfloat162float(ha));
    __nv_bfloat16 lb = __float2bfloat16(b - __bfloat162float(hb));
    hi = (u32)__bfloat16_as_ushort(ha) | ((u32)__bfloat16_as_ushort(hb) << 16);
    lo = (u32)__bfloat16_as_ushort(la) | ((u32)__bfloat16_as_ushort(lb) << 16);
}
DI void mma16816(float* c, u32 a0, u32 a1, u32 a2, u32 a3, u32 b0, u32 b1) {
    asm volatile(
        "mma.sync.aligned.m16n8k16.row.col.f32.bf16.bf16.f32 "
        "{%0,%1,%2,%3}, {%4,%5,%6,%7}, {%8,%9}, {%0,%1,%2,%3};"
        : "+f"(c[0]), "+f"(c[1]), "+f"(c[2]), "+f"(c[3])
        : "r"(a0), "r"(a1), "r"(a2), "r"(a3), "r"(b0), "r"(b1));
}
DI void ldsm4(u32& r0, u32& r1, u32& r2, u32& r3, u32 saddr) {
    asm volatile("ldmatrix.sync.aligned.m8n8.x4.shared.b16 {%0,%1,%2,%3}, [%4];"
                 : "=r"(r0), "=r"(r1), "=r"(r2), "=r"(r3) : "r"(saddr));
}
DI u32 smem_u32(const void* p) {
    u32 a;
    asm("{ .reg .u64 t; cvta.to.shared.u64 t, %1; cvt.u32.u64 %0, t; }" : "=r"(a) : "l"(p));
    return a;
}

// ---------------- weight packing ----------------
__global__ void pack_kernel(const float* __restrict__ Wu, const float* __restrict__ bu,
                            const float* __restrict__ Wg, const float* __restrict__ bg,
                            const float* __restrict__ Wa) {
    int i = blockIdx.x * blockDim.x + threadIdx.x;
    if (i < 192 * 304) {
        int n = i / 304, k = i % 304;
        float v = 0.f;
        if (k < 300) {
            if (n < 64)       v = Wu[k * 64 + n];
            else if (n < 128) v = Wg[k * 64 + (n - 64)];
            else              v = Wa[k * 64 + (n - 128)];
        }
        __nv_bfloat16 h = __float2bfloat16(v);
        g_WtH[i] = __bfloat16_as_ushort(h);
        g_WtL[i] = __bfloat16_as_ushort(__float2bfloat16(v - __bfloat162float(h)));
    }
    if (i < 192) g_bias[i] = (i < 64) ? bu[i] : (i < 128 ? bg[i - 64] : 0.f);
    if (i < 64 * 64) {
        int k = i / 64, j = i % 64;
        g_hW2[i] = make_float2(Wg[(300 + k) * 64 + j], Wa[(300 + k) * 64 + j]);
    }
}

// ---------------- full-N mma GEMM: pre = x @ Wcat + bias ----------------
// grid (512, 2) = (mblk, inp); 384 threads = 12 warps (4m x 3n), warp tile 32x64.
// Dynamic smem, 2 stages of [AH|AL|BH|BL], stride 24 ushorts per row (conflict-free LDSM).
// Per-stage byte offsets: AH 0, AL 6144, BH 12288, BL 21504; stage size 30720 B.
#define STG_BYTES 30720
__global__ void __launch_bounds__(384) gemm_mma_kernel(const float* __restrict__ x1,
                                                       const float* __restrict__ x2) {
    extern __shared__ __align__(16) unsigned short dyns[];
    __shared__ float bias_s[192];

    const int tid = threadIdx.x, lane = tid & 31, wid = tid >> 5;
    const int warp_m = wid & 3, warp_n = wid >> 2;          // 4 x 3
    const int mblk = blockIdx.x, inp = blockIdx.y;
    const float* __restrict__ X = inp ? x2 : x1;
    const size_t m0 = (size_t)mblk * 128u;
    float* __restrict__ outp = g_pre + ((size_t)inp * 65536u + m0) * 192u;

    if (tid < 192) bias_s[tid] = g_bias[tid];

    const u32 sb = smem_u32(dyns);

    // loader maps
    const int a_r = tid >> 1, a_kh = tid & 1;          // A: threads 0..255
    const int b_part = tid >= 192;                     // B: all 384 threads
    const int b_n = tid - b_part * 192;
    const unsigned short* __restrict__ Wsrc = b_part ? g_WtL : g_WtH;

    float c[2][8][4];
#pragma unroll
    for (int i = 0; i < 2; i++)
#pragma unroll
        for (int j = 0; j < 8; j++)
#pragma unroll
            for (int q = 0; q < 4; q++) c[i][j][q] = 0.f;

    // prefetch k-step 0
    float4 av0 = make_float4(0.f, 0.f, 0.f, 0.f), av1 = av0;
    uint4 bv0, bv1;
    if (tid < 256) {
        int kg = a_kh * 8;
        av0 = *(const float4*)&X[(m0 + a_r) * 300 + kg];
        av1 = *(const float4*)&X[(m0 + a_r) * 300 + kg + 4];
    }
    bv0 = *(const uint4*)&Wsrc[b_n * 304 + 0];
    bv1 = *(const uint4*)&Wsrc[b_n * 304 + 8];

    // ldsm lane address components
    const int l15 = lane & 15, lkh = (lane >> 4) * 8;

    for (int ck = 0; ck < 19; ck++) {
        const u32 stb = sb + (u32)(ck & 1) * STG_BYTES;
        // ---- STS stage ----
        if (tid < 256) {
            u32 h0, l0, h1, l1, h2, l2, h3, l3;
            split2(av0.x, av0.y, h0, l0);
            split2(av0.z, av0.w, h1, l1);
            split2(av1.x, av1.y, h2, l2);
            split2(av1.z, av1.w, h3, l3);
            u32 aoff = stb + (u32)(a_r * 48 + a_kh * 16);
            asm volatile("st.shared.v4.b32 [%0], {%1,%2,%3,%4};" ::
                         "r"(aoff), "r"(h0), "r"(h1), "r"(h2), "r"(h3) : "memory");
            asm volatile("st.shared.v4.b32 [%0], {%1,%2,%3,%4};" ::
                         "r"(aoff + 6144u), "r"(l0), "r"(l1), "r"(l2), "r"(l3) : "memory");
        }
        {
            u32 boff = stb + 12288u + (u32)b_part * 9216u + (u32)(b_n * 48);
            asm volatile("st.shared.v4.b32 [%0], {%1,%2,%3,%4};" ::
                         "r"(boff), "r"(bv0.x), "r"(bv0.y), "r"(bv0.z), "r"(bv0.w) : "memory");
            asm volatile("st.shared.v4.b32 [%0], {%1,%2,%3,%4};" ::
                         "r"(boff + 16u), "r"(bv1.x), "r"(bv1.y), "r"(bv1.z), "r"(bv1.w) : "memory");
        }
        // ---- prefetch k-step ck+1 ----
        if (ck < 18) {
            int kg = (ck + 1) * 16;
            if (tid < 256) {
                int k0 = kg + a_kh * 8;
                av0 = *(const float4*)&X[(m0 + a_r) * 300 + k0];
                av1 = (k0 + 7 < 300) ? *(const float4*)&X[(m0 + a_r) * 300 + k0 + 4]
                                     : make_float4(0.f, 0.f, 0.f, 0.f);
            }
            bv0 = *(const uint4*)&Wsrc[b_n * 304 + kg];
            bv1 = *(const uint4*)&Wsrc[b_n * 304 + kg + 8];
        }
        __syncthreads();
        // ---- compute stage (stage reuse at distance 2 is safe: next iter's sync
        //      separates this compute from the STS that overwrites this stage) ----
        u32 ah[2][4], al[2][4];
#pragma unroll
        for (int mf = 0; mf < 2; mf++) {
            u32 aaddr = stb + (u32)((warp_m * 32 + mf * 16 + l15) * 48 + lkh * 2);
            ldsm4(ah[mf][0], ah[mf][1], ah[mf][2], ah[mf][3], aaddr);
            ldsm4(al[mf][0], al[mf][1], al[mf][2], al[mf][3], aaddr + 6144u);
        }
#pragma unroll
        for (int nf2 = 0; nf2 < 4; nf2++) {
            u32 baddr = stb + 12288u + (u32)((warp_n * 64 + nf2 * 16 + l15) * 48 + lkh * 2);
            u32 bh0, bh1, bh2, bh3, bl0, bl1, bl2, bl3;
            ldsm4(bh0, bh1, bh2, bh3, baddr);            // r0,r2 = nfrag0 b0,b1; r1,r3 = nfrag1
            ldsm4(bl0, bl1, bl2, bl3, baddr + 9216u);
#pragma unroll
            for (int mf = 0; mf < 2; mf++) {
                float* c0 = c[mf][nf2 * 2 + 0];
                float* c1 = c[mf][nf2 * 2 + 1];
                mma16816(c0, ah[mf][0], ah[mf][1], ah[mf][2], ah[mf][3], bh0, bh2);
                mma16816(c0, ah[mf][0], ah[mf][1], ah[mf][2], ah[mf][3], bl0, bl2);
                mma16816(c0, al[mf][0], al[mf][1], al[mf][2], al[mf][3], bh0, bh2);
                mma16816(c1, ah[mf][0], ah[mf][1], ah[mf][2], ah[mf][3], bh1, bh3);
                mma16816(c1, ah[mf][0], ah[mf][1], ah[mf][2], ah[mf][3], bl1, bl3);
                mma16816(c1, al[mf][0], al[mf][1], al[mf][2], al[mf][3], bh1, bh3);
            }
        }
    }

    // ---- epilogue: +bias, write g_pre ----
#pragma unroll
    for (int mf = 0; mf < 2; mf++) {
#pragma unroll
        for (int nf = 0; nf < 8; nf++) {
            int row = warp_m * 32 + mf * 16 + (lane >> 2);
            int col = warp_n * 64 + nf * 8 + 2 * (lane & 3);
            float bx = bias_s[col], by = bias_s[col + 1];
            float2 v0 = make_float2(c[mf][nf][0] + bx, c[mf][nf][1] + by);
            float2 v1 = make_float2(c[mf][nf][2] + bx, c[mf][nf][3] + by);
            *(float2*)&outp[(size_t)row * 192 + col] = v0;
            *(float2*)&outp[(size_t)(row + 8) * 192 + col] = v1;
        }
    }
}

// ---------------- sequential recurrence ----------------
__global__ void __launch_bounds__(256) recur_kernel(const float* __restrict__ s) {
    __shared__ float2 W2s[64 * 64];
    __shared__ float  hbuf[2][64][10];

    const int tid = threadIdx.x;
    const int j = tid & 63, grp = tid >> 6;

    for (int i = tid; i < 4096; i += 256) W2s[i] = g_hW2[i];

    const int ls0 = grp * 2, ls1 = ls0 + 1;
    const int sidx0 = blockIdx.x * 8 + ls0;
    const int sidx1 = sidx0 + 1;
    const float* __restrict__ pre0 = g_pre + (size_t)sidx0 * 128u * 192u;
    const float* __restrict__ pre1 = g_pre + (size_t)sidx1 * 128u * 192u;

    const float h0 = tanhf(s[j]);
    float n0 = 0.f, dd0 = 0.f, am0 = -1e38f, hf0 = h0;
    float n1 = 0.f, dd1 = 0.f, am1 = -1e38f, hf1 = h0;

    hbuf[0][j][ls0] = h0;
    hbuf[0][j][ls1] = h0;
    __syncthreads();
    int p = 0;

    float u0 = pre0[j], gg0 = pre0[64 + j], aa0 = pre0[128 + j];
    float u1 = pre1[j], gg1 = pre1[64 + j], aa1 = pre1[128 + j];

    for (int t = 0; t < 128; t++) {
        float nu0 = 0.f, ng0 = 0.f, na0 = 0.f, nu1 = 0.f, ng1 = 0.f, na1 = 0.f;
        if (t < 127) {
            const float* q0 = pre0 + (size_t)(t + 1) * 192;
            const float* q1 = pre1 + (size_t)(t + 1) * 192;
            nu0 = q0[j]; ng0 = q0[64 + j]; na0 = q0[128 + j];
            nu1 = q1[j]; ng1 = q1[64 + j]; na1 = q1[128 + j];
        }

        u64 acc0 = pack2(gg0, aa0);
        u64 acc1 = pack2(gg1, aa1);
#pragma unroll
        for (int k = 0; k < 64; k++) {
            u64 w = *(const u64*)&W2s[k * 64 + j];
            float2 hh = *(const float2*)&hbuf[p][k][ls0];
            acc0 = f32x2_fma(pack2(hh.x, hh.x), w, acc0);
            acc1 = f32x2_fma(pack2(hh.y, hh.y), w, acc1);
        }
        float2 ga0 = unpack2(acc0), ga1 = unpack2(acc1);

        {
            float z  = u0 * tanhf(ga0.x);
            float an = fmaxf(am0, ga0.y);
            float eo = __expf(am0 - an);
            float ea = __expf(ga0.y - an);
            n0  = n0 * eo + z * ea;
            dd0 = dd0 * eo + ea;
            am0 = an;
            hf0 = tanhf(n0 / dd0);
            hbuf[p ^ 1][j][ls0] = hf0;
        }
        {
            float z  = u1 * tanhf(ga1.x);
            float an = fmaxf(am1, ga1.y);
            float eo = __expf(am1 - an);
            float ea = __expf(ga1.y - an);
            n1  = n1 * eo + z * ea;
            dd1 = dd1 * eo + ea;
            am1 = an;
            hf1 = tanhf(n1 / dd1);
            hbuf[p ^ 1][j][ls1] = hf1;
        }
        __syncthreads();
        p ^= 1;
        u0 = nu0; gg0 = ng0; aa0 = na0;
        u1 = nu1; gg1 = ng1; aa1 = na1;
    }

    {
        int inp = sidx0 >> 9, b = sidx0 & 511;
        g_hn[b * 128 + inp * 64 + j] = hf0;
    }
    {
        int inp = sidx1 >> 9, b = sidx1 & 511;
        g_hn[b * 128 + inp * 64 + j] = hf1;
    }
}

// ---------------- batchnorm stats ----------------
__global__ void bnstats_kernel() {
    const int c = blockIdx.x;
    const int tid = threadIdx.x;
    float s = 0.f, sq = 0.f;
#pragma unroll
    for (int r = tid; r < 512; r += 256) {
        float v = g_hn[r * 128 + c];
        s += v; sq += v * v;
    }
#pragma unroll
    for (int o = 16; o; o >>= 1) {
        s  += __shfl_down_sync(0xffffffffu, s, o);
        sq += __shfl_down_sync(0xffffffffu, sq, o);
    }
    __shared__ float ss[8], qs[8];
    if ((tid & 31) == 0) { ss[tid >> 5] = s; qs[tid >> 5] = sq; }
    __syncthreads();
    if (tid == 0) {
        float S = 0.f, Q = 0.f;
#pragma unroll
        for (int w = 0; w < 8; w++) { S += ss[w]; Q += qs[w]; }
        float mean = S * (1.f / 512.f);
        float var  = Q * (1.f / 512.f) - mean * mean;
        g_bnm[c] = mean;
        g_bnr[c] = rsqrtf(var + 1e-5f);
    }
}

// ---------------- head ----------------
__global__ void head_kernel(const float* __restrict__ W1, const float* __restrict__ b1,
                            const float* __restrict__ pw, const float* __restrict__ W2,
                            const float* __restrict__ b2, float* __restrict__ out) {
    const int r = blockIdx.x;
    const int t = threadIdx.x;
    __shared__ float xs[128];
    for (int k = t; k < 128; k += 64)
        xs[k] = (g_hn[r * 128 + k] - g_bnm[k]) * g_bnr[k];
    __syncthreads();

    float acc = b1[t];
#pragma unroll
    for (int k = 0; k < 128; k++)
        acc = fmaf(xs[k], W1[k * 64 + t], acc);
    float pwv = *pw;
    acc = (acc >= 0.f) ? acc : pwv * acc;
    float v = acc * W2[t];
#pragma unroll
    for (int o = 16; o; o >>= 1) v += __shfl_down_sync(0xffffffffu, v, o);
    __shared__ float red[2];
    if ((t & 31) == 0) red[t >> 5] = v;
    __syncthreads();
    if (t == 0) {
        float sum = red[0] + red[1] + b2[0];
        out[r] = 1.f / (1.f + __expf(-sum));
    }
}

// ---------------- launch ----------------
extern "C" void kernel_launch(void* const* d_in, const int* in_sizes, int n_in,
                              void* d_out, int out_size) {
    const float* in1 = (const float*)d_in[0];
    const float* in2 = (const float*)d_in[1];
    const float* Wu  = (const float*)d_in[2];
    const float* bu  = (const float*)d_in[3];
    const float* Wg  = (const float*)d_in[4];
    const float* bg  = (const float*)d_in[5];
    const float* Wa  = (const float*)d_in[6];
    const float* s   = (const float*)d_in[7];
    const float* W1  = (const float*)d_in[8];
    const float* b1  = (const float*)d_in[9];
    const float* pw  = (const float*)d_in[10];
    const float* W2  = (const float*)d_in[11];
    const float* b2  = (const float*)d_in[12];
    float* out = (float*)d_out;

    cudaFuncSetAttribute(gemm_mma_kernel, cudaFuncAttributeMaxDynamicSharedMemorySize,
                         2 * STG_BYTES);

    pack_kernel<<<229, 256>>>(Wu, bu, Wg, bg, Wa);
    gemm_mma_kernel<<<dim3(512, 2), 384, 2 * STG_BYTES>>>(in1, in2);
    recur_kernel<<<128, 256>>>(s);
    bnstats_kernel<<<128, 256>>>();
    head_kernel<<<512, 64>>>(W1, b1, pw, W2, b2, out);
}

// round 9
// speedup vs baseline: 1.4297x; 1.0721x over previous
#include <cuda_runtime.h>
#include <cuda_bf16.h>

#define DI __device__ __forceinline__
typedef unsigned int u32;
typedef unsigned long long u64;

// B=512, T=128, D=300, H=64. M=65536 rows/input, 192 fused cols (u|g|a).
// GEMM: CTA = 128 rows x 192 cols, K 300->304->pad320, 10 k32 pipeline stages.
// Split-bf16 (hi/lo, 3 products) mma.sync for fp32-level accuracy.

// ---------------- device-global scratch ----------------
__device__ float          g_pre[2u * 65536u * 192u];   // [input][row][192]
__device__ unsigned short g_WtH[192 * 304];            // W^T hi bf16 [n][k], zero-pad k>=300
__device__ unsigned short g_WtL[192 * 304];            // W^T lo bf16
__device__ float          g_bias[192];                 // bu | bg | 0
__device__ float2         g_hW2[64 * 64];              // [k][j] = {Wg_h, Wa_h}
__device__ float          g_hn[512 * 128];
__device__ float          g_bnm[128];
__device__ float          g_bnr[128];

// ---------------- helpers ----------------
DI u64 f32x2_fma(u64 a, u64 b, u64 c) {
    u64 d;
    asm("fma.rn.f32x2 %0, %1, %2, %3;" : "=l"(d) : "l"(a), "l"(b), "l"(c));
    return d;
}
DI u64 pack2(float x, float y) {
    u64 r;
    asm("mov.b64 %0, {%1, %2};" : "=l"(r) : "f"(x), "f"(y));
    return r;
}
DI float2 unpack2(u64 v) {
    float2 f;
    asm("mov.b64 {%0, %1}, %2;" : "=f"(f.x), "=f"(f.y) : "l"(v));
    return f;
}
DI void split2(float a, float b, u32& hi, u32& lo) {
    __nv_bfloat16 ha = __float2bfloat16(a), hb = __float2bfloat16(b);
    __nv_bfloat16 la = __float2bfloat16(a - __bfloat162float(ha));
    __nv_bfloat16 lb = __float2bfloat16(b - __bfloat162float(hb));
    hi = (u32)__bfloat16_as_ushort(ha) | ((u32)__bfloat16_as_ushort(hb) << 16);
    lo = (u32)__bfloat16_as_ushort(la) | ((u32)__bfloat16_as_ushort(lb) << 16);
}
DI void mma16816(float* c, u32 a0, u32 a1, u32 a2, u32 a3, u32 b0, u32 b1) {
    asm volatile(
        "mma.sync.aligned.m16n8k16.row.col.f32.bf16.bf16.f32 "
        "{%0,%1,%2,%3}, {%4,%5,%6,%7}, {%8,%9}, {%0,%1,%2,%3};"
        : "+f"(c[0]), "+f"(c[1]), "+f"(c[2]), "+f"(c[3])
        : "r"(a0), "r"(a1), "r"(a2), "r"(a3), "r"(b0), "r"(b1));
}
DI void ldsm4(u32& r0, u32& r1, u32& r2, u32& r3, u32 saddr) {
    asm volatile("ldmatrix.sync.aligned.m8n8.x4.shared.b16 {%0,%1,%2,%3}, [%4];"
                 : "=r"(r0), "=r"(r1), "=r"(r2), "=r"(r3) : "r"(saddr));
}
DI u32 smem_u32(const void* p) {
    u32 a;
    asm("{ .reg .u64 t; cvta.to.shared.u64 t, %1; cvt.u32.u64 %0, t; }" : "=r"(a) : "l"(p));
    return a;
}

// ---------------- weight packing ----------------
__global__ void pack_kernel(const float* __restrict__ Wu, const float* __restrict__ bu,
                            const float* __restrict__ Wg, const float* __restrict__ bg,
                            const float* __restrict__ Wa) {
    int i = blockIdx.x * blockDim.x + threadIdx.x;
    if (i < 192 * 304) {
        int n = i / 304, k = i % 304;
        float v = 0.f;
        if (k < 300) {
            if (n < 64)       v = Wu[k * 64 + n];
            else if (n < 128) v = Wg[k * 64 + (n - 64)];
            else              v = Wa[k * 64 + (n - 128)];
        }
        __nv_bfloat16 h = __float2bfloat16(v);
        g_WtH[i] = __bfloat16_as_ushort(h);
        g_WtL[i] = __bfloat16_as_ushort(__float2bfloat16(v - __bfloat162float(h)));
    }
    if (i < 192) g_bias[i] = (i < 64) ? bu[i] : (i < 128 ? bg[i - 64] : 0.f);
    if (i < 64 * 64) {
        int k = i / 64, j = i % 64;
        g_hW2[i] = make_float2(Wg[(300 + k) * 64 + j], Wa[(300 + k) * 64 + j]);
    }
}

// ---------------- full-N mma GEMM, k32 stages: pre = x @ Wcat + bias ----------------
// grid (512, 2); 384 threads = 12 warps (4m x 3n), warp tile 32x64.
// Stage (51200 B): AH 0 (128x80B), AL 10240, BH 20480 (192x80B), BL 35840. 2 stages.
// Row stride 80 B => 8 consecutive rows hit 8 distinct 16B bank-groups (conflict-free LDSM).
#define STG_BYTES 51200u
__global__ void __launch_bounds__(384) gemm_mma_kernel(const float* __restrict__ x1,
                                                       const float* __restrict__ x2) {
    extern __shared__ __align__(16) unsigned short dyns[];
    __shared__ float bias_s[192];

    const int tid = threadIdx.x, lane = tid & 31, wid = tid >> 5;
    const int warp_m = wid & 3, warp_n = wid >> 2;
    const int mblk = blockIdx.x, inp = blockIdx.y;
    const float* __restrict__ X = inp ? x2 : x1;
    const size_t m0 = (size_t)mblk * 128u;
    float* __restrict__ outp = g_pre + ((size_t)inp * 65536u + m0) * 192u;

    if (tid < 192) bias_s[tid] = g_bias[tid];

    const u32 sb = smem_u32(dyns);

    // loader maps
    const int a_r = tid >> 1, a_q = tid & 1;          // A: threads 0..255, 16 k each
    const int b_part = tid >= 192;                    // B: all 384 threads, 32 k each
    const int b_n = tid - b_part * 192;
    const unsigned short* __restrict__ Wsrc = b_part ? g_WtL : g_WtH;

    float c[2][8][4];
#pragma unroll
    for (int i = 0; i < 2; i++)
#pragma unroll
        for (int j = 0; j < 8; j++)
#pragma unroll
            for (int q = 0; q < 4; q++) c[i][j][q] = 0.f;

    // prefetch stage 0
    float4 av[4];
    uint4 bv[4];
    {
        const int kb = a_q * 16;
#pragma unroll
        for (int cc = 0; cc < 4; cc++) {
            int k0 = kb + cc * 4;
            av[cc] = (tid < 256 && k0 < 300) ? *(const float4*)&X[(m0 + a_r) * 300 + k0]
                                             : make_float4(0.f, 0.f, 0.f, 0.f);
        }
#pragma unroll
        for (int cc = 0; cc < 4; cc++) {
            int k0 = cc * 8;
            bv[cc] = *(const uint4*)&Wsrc[b_n * 304 + k0];
        }
    }

    const int l15 = lane & 15, lkh16 = (lane >> 4) * 16;   // byte offset of k-half

    for (int ck = 0; ck < 10; ck++) {
        const u32 stb = sb + (u32)(ck & 1) * STG_BYTES;
        // ---- STS stage ----
        if (tid < 256) {
            u32 h[8], l[8];
#pragma unroll
            for (int cc = 0; cc < 4; cc++) {
                split2(av[cc].x, av[cc].y, h[cc * 2], l[cc * 2]);
                split2(av[cc].z, av[cc].w, h[cc * 2 + 1], l[cc * 2 + 1]);
            }
            u32 aoff = stb + (u32)(a_r * 80 + a_q * 32);
            asm volatile("st.shared.v4.b32 [%0], {%1,%2,%3,%4};" ::
                         "r"(aoff), "r"(h[0]), "r"(h[1]), "r"(h[2]), "r"(h[3]) : "memory");
            asm volatile("st.shared.v4.b32 [%0], {%1,%2,%3,%4};" ::
                         "r"(aoff + 16u), "r"(h[4]), "r"(h[5]), "r"(h[6]), "r"(h[7]) : "memory");
            asm volatile("st.shared.v4.b32 [%0], {%1,%2,%3,%4};" ::
                         "r"(aoff + 10240u), "r"(l[0]), "r"(l[1]), "r"(l[2]), "r"(l[3]) : "memory");
            asm volatile("st.shared.v4.b32 [%0], {%1,%2,%3,%4};" ::
                         "r"(aoff + 10256u), "r"(l[4]), "r"(l[5]), "r"(l[6]), "r"(l[7]) : "memory");
        }
        {
            u32 boff = stb + 20480u + (u32)b_part * 15360u + (u32)(b_n * 80);
#pragma unroll
            for (int cc = 0; cc < 4; cc++)
                asm volatile("st.shared.v4.b32 [%0], {%1,%2,%3,%4};" ::
                             "r"(boff + (u32)cc * 16u),
                             "r"(bv[cc].x), "r"(bv[cc].y), "r"(bv[cc].z), "r"(bv[cc].w) : "memory");
        }
        // ---- prefetch stage ck+1 ----
        if (ck < 9) {
            const int kg = (ck + 1) * 32;
            const int kb = kg + a_q * 16;
#pragma unroll
            for (int cc = 0; cc < 4; cc++) {
                int k0 = kb + cc * 4;
                av[cc] = (tid < 256 && k0 < 300) ? *(const float4*)&X[(m0 + a_r) * 300 + k0]
                                                 : make_float4(0.f, 0.f, 0.f, 0.f);
            }
#pragma unroll
            for (int cc = 0; cc < 4; cc++) {
                int k0 = kg + cc * 8;
                bv[cc] = (k0 < 304) ? *(const uint4*)&Wsrc[b_n * 304 + k0]
                                    : make_uint4(0u, 0u, 0u, 0u);
            }
        }
        __syncthreads();
        // ---- compute: two k16 subtiles (one for the last stage) ----
        const int nkk = (ck < 9) ? 2 : 1;
        for (int kk = 0; kk < nkk; kk++) {
            const u32 ko = (u32)kk * 32u;
            u32 ah[2][4], al[2][4];
#pragma unroll
            for (int mf = 0; mf < 2; mf++) {
                u32 aaddr = stb + (u32)((warp_m * 32 + mf * 16 + l15) * 80) + ko + (u32)lkh16;
                ldsm4(ah[mf][0], ah[mf][1], ah[mf][2], ah[mf][3], aaddr);
                ldsm4(al[mf][0], al[mf][1], al[mf][2], al[mf][3], aaddr + 10240u);
            }
#pragma unroll
            for (int nf2 = 0; nf2 < 4; nf2++) {
                u32 baddr = stb + 20480u + (u32)((warp_n * 64 + nf2 * 16 + l15) * 80) + ko + (u32)lkh16;
                u32 bh0, bh1, bh2, bh3, bl0, bl1, bl2, bl3;
                ldsm4(bh0, bh1, bh2, bh3, baddr);
                ldsm4(bl0, bl1, bl2, bl3, baddr + 15360u);
#pragma unroll
                for (int mf = 0; mf < 2; mf++) {
                    float* c0 = c[mf][nf2 * 2 + 0];
                    float* c1 = c[mf][nf2 * 2 + 1];
                    mma16816(c0, ah[mf][0], ah[mf][1], ah[mf][2], ah[mf][3], bh0, bh2);
                    mma16816(c0, ah[mf][0], ah[mf][1], ah[mf][2], ah[mf][3], bl0, bl2);
                    mma16816(c0, al[mf][0], al[mf][1], al[mf][2], al[mf][3], bh0, bh2);
                    mma16816(c1, ah[mf][0], ah[mf][1], ah[mf][2], ah[mf][3], bh1, bh3);
                    mma16816(c1, ah[mf][0], ah[mf][1], ah[mf][2], ah[mf][3], bl1, bl3);
                    mma16816(c1, al[mf][0], al[mf][1], al[mf][2], al[mf][3], bh1, bh3);
                }
            }
        }
    }

    // ---- epilogue: +bias, write g_pre ----
#pragma unroll
    for (int mf = 0; mf < 2; mf++) {
#pragma unroll
        for (int nf = 0; nf < 8; nf++) {
            int row = warp_m * 32 + mf * 16 + (lane >> 2);
            int col = warp_n * 64 + nf * 8 + 2 * (lane & 3);
            float bx = bias_s[col], by = bias_s[col + 1];
            float2 v0 = make_float2(c[mf][nf][0] + bx, c[mf][nf][1] + by);
            float2 v1 = make_float2(c[mf][nf][2] + bx, c[mf][nf][3] + by);
            *(float2*)&outp[(size_t)row * 192 + col] = v0;
            *(float2*)&outp[(size_t)(row + 8) * 192 + col] = v1;
        }
    }
}

// ---------------- sequential recurrence: 4 seqs/thread, dup-h, f32x2 ----------------
// 128 blocks x 128 threads. Thread (j = tid&63, grp = tid>>6) handles seqs grp*4..+3
// of block-group blockIdx.x*8. hbuf stores {h,h} u64 per (k, seq): inner loop has
// zero packs: acc{g,a} += {h,h} * {wg,wa}.
__global__ void __launch_bounds__(128) recur_kernel(const float* __restrict__ s) {
    __shared__ float2 W2s[64 * 64];                         // 32 KB
    __shared__ __align__(16) u64 hbuf[2][64][9];            // 9216 B (9-slot rows de-conflict stores)

    const int tid = threadIdx.x;
    const int j = tid & 63, grp = tid >> 6;

    for (int i = tid; i < 4096; i += 128) W2s[i] = g_hW2[i];

    const int ls0 = grp * 4;
    const int sbase = blockIdx.x * 8 + ls0;
    const float* __restrict__ pre[4];
#pragma unroll
    for (int i = 0; i < 4; i++) pre[i] = g_pre + (size_t)(sbase + i) * 24576u;

    const float h0 = tanhf(s[j]);
    const u64 h0d = pack2(h0, h0);
    float n[4], d[4], am[4], hf[4];
#pragma unroll
    for (int i = 0; i < 4; i++) {
        n[i] = 0.f; d[i] = 0.f; am[i] = -1e38f; hf[i] = h0;
        hbuf[0][j][ls0 + i] = h0d;
    }
    __syncthreads();
    int p = 0;

    float u[4], g[4], a[4];
#pragma unroll
    for (int i = 0; i < 4; i++) {
        u[i] = pre[i][j]; g[i] = pre[i][64 + j]; a[i] = pre[i][128 + j];
    }

    const int barid = grp + 1;   // named barrier per grp (2 warps = 64 threads)

    for (int t = 0; t < 128; t++) {
        float nu[4], ng[4], na[4];
        if (t < 127) {
#pragma unroll
            for (int i = 0; i < 4; i++) {
                const float* q = pre[i] + (size_t)(t + 1) * 192;
                nu[i] = q[j]; ng[i] = q[64 + j]; na[i] = q[128 + j];
            }
        }

        u64 acc0 = pack2(g[0], a[0]), acc1 = pack2(g[1], a[1]);
        u64 acc2 = pack2(g[2], a[2]), acc3 = pack2(g[3], a[3]);
#pragma unroll
        for (int k = 0; k < 64; k++) {
            u64 w = *(const u64*)&W2s[k * 64 + j];
            const u64* hrow = &hbuf[p][k][ls0];
            acc0 = f32x2_fma(hrow[0], w, acc0);
            acc1 = f32x2_fma(hrow[1], w, acc1);
            acc2 = f32x2_fma(hrow[2], w, acc2);
            acc3 = f32x2_fma(hrow[3], w, acc3);
        }
        u64 accv[4] = {acc0, acc1, acc2, acc3};
#pragma unroll
        for (int i = 0; i < 4; i++) {
            float2 ga = unpack2(accv[i]);
            float z  = u[i] * tanhf(ga.x);
            float an = fmaxf(am[i], ga.y);
            float eo = __expf(am[i] - an);
            float ea = __expf(ga.y - an);
            n[i] = n[i] * eo + z * ea;
            d[i] = d[i] * eo + ea;
            am[i] = an;
            hf[i] = tanhf(n[i] / d[i]);
            hbuf[p ^ 1][j][ls0 + i] = pack2(hf[i], hf[i]);
        }
        asm volatile("bar.sync %0, 64;" :: "r"(barid) : "memory");
        p ^= 1;
#pragma unroll
        for (int i = 0; i < 4; i++) { u[i] = nu[i]; g[i] = ng[i]; a[i] = na[i]; }
    }

#pragma unroll
    for (int i = 0; i < 4; i++) {
        int sidx = sbase + i;
        g_hn[(sidx & 511) * 128 + (sidx >> 9) * 64 + j] = hf[i];
    }
}

// ---------------- batchnorm stats ----------------
__global__ void bnstats_kernel() {
    const int c = blockIdx.x;
    const int tid = threadIdx.x;
    float s = 0.f, sq = 0.f;
#pragma unroll
    for (int r = tid; r < 512; r += 256) {
        float v = g_hn[r * 128 + c];
        s += v; sq += v * v;
    }
#pragma unroll
    for (int o = 16; o; o >>= 1) {
        s  += __shfl_down_sync(0xffffffffu, s, o);
        sq += __shfl_down_sync(0xffffffffu, sq, o);
    }
    __shared__ float ss[8], qs[8];
    if ((tid & 31) == 0) { ss[tid >> 5] = s; qs[tid >> 5] = sq; }
    __syncthreads();
    if (tid == 0) {
        float S = 0.f, Q = 0.f;
#pragma unroll
        for (int w = 0; w < 8; w++) { S += ss[w]; Q += qs[w]; }
        float mean = S * (1.f / 512.f);
        float var  = Q * (1.f / 512.f) - mean * mean;
        g_bnm[c] = mean;
        g_bnr[c] = rsqrtf(var + 1e-5f);
    }
}

// ---------------- head ----------------
__global__ void head_kernel(const float* __restrict__ W1, const float* __restrict__ b1,
                            const float* __restrict__ pw, const float* __restrict__ W2,
                            const float* __restrict__ b2, float* __restrict__ out) {
    const int r = blockIdx.x;
    const int t = threadIdx.x;
    __shared__ float xs[128];
    for (int k = t; k < 128; k += 64)
        xs[k] = (g_hn[r * 128 + k] - g_bnm[k]) * g_bnr[k];
    __syncthreads();

    float acc = b1[t];
#pragma unroll
    for (int k = 0; k < 128; k++)
        acc = fmaf(xs[k], W1[k * 64 + t], acc);
    float pwv = *pw;
    acc = (acc >= 0.f) ? acc : pwv * acc;
    float v = acc * W2[t];
#pragma unroll
    for (int o = 16; o; o >>= 1) v += __shfl_down_sync(0xffffffffu, v, o);
    __shared__ float red[2];
    if ((t & 31) == 0) red[t >> 5] = v;
    __syncthreads();
    if (t == 0) {
        float sum = red[0] + red[1] + b2[0];
        out[r] = 1.f / (1.f + __expf(-sum));
    }
}

// ---------------- launch ----------------
extern "C" void kernel_launch(void* const* d_in, const int* in_sizes, int n_in,
                              void* d_out, int out_size) {
    const float* in1 = (const float*)d_in[0];
    const float* in2 = (const float*)d_in[1];
    const float* Wu  = (const float*)d_in[2];
    const float* bu  = (const float*)d_in[3];
    const float* Wg  = (const float*)d_in[4];
    const float* bg  = (const float*)d_in[5];
    const float* Wa  = (const float*)d_in[6];
    const float* s   = (const float*)d_in[7];
    const float* W1  = (const float*)d_in[8];
    const float* b1  = (const float*)d_in[9];
    const float* pw  = (const float*)d_in[10];
    const float* W2  = (const float*)d_in[11];
    const float* b2  = (const float*)d_in[12];
    float* out = (float*)d_out;

    cudaFuncSetAttribute(gemm_mma_kernel, cudaFuncAttributeMaxDynamicSharedMemorySize,
                         2 * STG_BYTES);

    pack_kernel<<<229, 256>>>(Wu, bu, Wg, bg, Wa);
    gemm_mma_kernel<<<dim3(512, 2), 384, 2 * STG_BYTES>>>(in1, in2);
    recur_kernel<<<128, 128>>>(s);
    bnstats_kernel<<<128, 256>>>();
    head_kernel<<<512, 64>>>(W1, b1, pw, W2, b2, out);
}

// round 11
// speedup vs baseline: 1.6220x; 1.1345x over previous
#include <cuda_runtime.h>
#include <cuda_fp16.h>

#define DI __device__ __forceinline__
typedef unsigned int u32;
typedef unsigned long long u64;

// B=512, T=128, D=300, H=64. M=65536 rows/input, 192 fused cols (u|g|a).
// GEMM: CTA = 128 rows x 192 cols, K 300->304, 10 k32 pipeline stages.
// fp16 split on A only (Ah+Al), B in fp16-hi: D = A*Bh, rel err ~1.4e-4.

// ---------------- device-global scratch ----------------
__device__ float          g_pre[2u * 65536u * 192u];   // [input][row][192]
__device__ unsigned short g_WtH[192 * 304];            // W^T fp16 [n][k], zero-pad k>=300
__device__ float          g_bias[192];                 // bu | bg | 0
__device__ float2         g_hW2[64 * 64];              // [k][j] = {Wg_h, Wa_h}
__device__ float          g_hn[512 * 128];
__device__ float          g_bnm[128];
__device__ float          g_bnr[128];

// ---------------- helpers ----------------
DI u64 f32x2_fma(u64 a, u64 b, u64 c) {
    u64 d;
    asm("fma.rn.f32x2 %0, %1, %2, %3;" : "=l"(d) : "l"(a), "l"(b), "l"(c));
    return d;
}
DI u64 pack2(float x, float y) {
    u64 r;
    asm("mov.b64 %0, {%1, %2};" : "=l"(r) : "f"(x), "f"(y));
    return r;
}
DI float2 unpack2(u64 v) {
    float2 f;
    asm("mov.b64 {%0, %1}, %2;" : "=f"(f.x), "=f"(f.y) : "l"(v));
    return f;
}
// split two floats into packed fp16 hi and lo
DI void split2h(float a, float b, u32& hi, u32& lo) {
    __half ha = __float2half_rn(a), hb = __float2half_rn(b);
    __half la = __float2half_rn(a - __half2float(ha));
    __half lb = __float2half_rn(b - __half2float(hb));
    hi = (u32)__half_as_ushort(ha) | ((u32)__half_as_ushort(hb) << 16);
    lo = (u32)__half_as_ushort(la) | ((u32)__half_as_ushort(lb) << 16);
}
DI void mma16816(float* c, u32 a0, u32 a1, u32 a2, u32 a3, u32 b0, u32 b1) {
    asm volatile(
        "mma.sync.aligned.m16n8k16.row.col.f32.f16.f16.f32 "
        "{%0,%1,%2,%3}, {%4,%5,%6,%7}, {%8,%9}, {%0,%1,%2,%3};"
        : "+f"(c[0]), "+f"(c[1]), "+f"(c[2]), "+f"(c[3])
        : "r"(a0), "r"(a1), "r"(a2), "r"(a3), "r"(b0), "r"(b1));
}
DI void ldsm4(u32& r0, u32& r1, u32& r2, u32& r3, u32 saddr) {
    asm volatile("ldmatrix.sync.aligned.m8n8.x4.shared.b16 {%0,%1,%2,%3}, [%4];"
                 : "=r"(r0), "=r"(r1), "=r"(r2), "=r"(r3) : "r"(saddr));
}
DI u32 smem_u32(const void* p) {
    u32 a;
    asm("{ .reg .u64 t; cvta.to.shared.u64 t, %1; cvt.u32.u64 %0, t; }" : "=r"(a) : "l"(p));
    return a;
}

// ---------------- weight packing ----------------
__global__ void pack_kernel(const float* __restrict__ Wu, const float* __restrict__ bu,
                            const float* __restrict__ Wg, const float* __restrict__ bg,
                            const float* __restrict__ Wa) {
    int i = blockIdx.x * blockDim.x + threadIdx.x;
    if (i < 192 * 304) {
        int n = i / 304, k = i % 304;
        float v = 0.f;
        if (k < 300) {
            if (n < 64)       v = Wu[k * 64 + n];
            else if (n < 128) v = Wg[k * 64 + (n - 64)];
            else              v = Wa[k * 64 + (n - 128)];
        }
        g_WtH[i] = __half_as_ushort(__float2half_rn(v));
    }
    if (i < 192) g_bias[i] = (i < 64) ? bu[i] : (i < 128 ? bg[i - 64] : 0.f);
    if (i < 64 * 64) {
        int k = i / 64, j = i % 64;
        g_hW2[i] = make_float2(Wg[(300 + k) * 64 + j], Wa[(300 + k) * 64 + j]);
    }
}

// ---------------- full-N mma GEMM, k32 stages: pre = x @ Wcat + bias ----------------
// grid (512, 2); 384 threads = 12 warps (4m x 3n), warp tile 32x64.
// Stage (35840 B): AH 0 (128x80B), AL 10240, BH 20480 (192x80B). 2 stages.
// Row stride 80 B => 8 consecutive rows hit 8 distinct 16B bank-groups (conflict-free LDSM).
#define STG_BYTES 35840u
__global__ void __launch_bounds__(384) gemm_mma_kernel(const float* __restrict__ x1,
                                                       const float* __restrict__ x2) {
    extern __shared__ __align__(16) unsigned short dyns[];
    __shared__ float bias_s[192];

    const int tid = threadIdx.x, lane = tid & 31, wid = tid >> 5;
    const int warp_m = wid & 3, warp_n = wid >> 2;
    const int mblk = blockIdx.x, inp = blockIdx.y;
    const float* __restrict__ X = inp ? x2 : x1;
    const size_t m0 = (size_t)mblk * 128u;
    float* __restrict__ outp = g_pre + ((size_t)inp * 65536u + m0) * 192u;

    if (tid < 192) bias_s[tid] = g_bias[tid];

    const u32 sb = smem_u32(dyns);

    // loader maps
    const int a_r = tid >> 1, a_q = tid & 1;          // A: threads 0..255, 16 k each
    const int b_n = tid;                              // B: threads 0..191, full k32 row

    float c[2][8][4];
#pragma unroll
    for (int i = 0; i < 2; i++)
#pragma unroll
        for (int j = 0; j < 8; j++)
#pragma unroll
            for (int q = 0; q < 4; q++) c[i][j][q] = 0.f;

    // prefetch stage 0
    float4 av[4];
    uint4 bv[4];
    {
        const int kb = a_q * 16;
#pragma unroll
        for (int cc = 0; cc < 4; cc++) {
            int k0 = kb + cc * 4;
            av[cc] = (tid < 256 && k0 < 300) ? *(const float4*)&X[(m0 + a_r) * 300 + k0]
                                             : make_float4(0.f, 0.f, 0.f, 0.f);
        }
        if (tid < 192) {
#pragma unroll
            for (int cc = 0; cc < 4; cc++)
                bv[cc] = *(const uint4*)&g_WtH[b_n * 304 + cc * 8];
        }
    }

    const int l15 = lane & 15, lkh16 = (lane >> 4) * 16;   // byte offset of k-half

    for (int ck = 0; ck < 10; ck++) {
        const u32 stb = sb + (u32)(ck & 1) * STG_BYTES;
        // ---- STS stage ----
        if (tid < 256) {
            u32 h[8], l[8];
#pragma unroll
            for (int cc = 0; cc < 4; cc++) {
                split2h(av[cc].x, av[cc].y, h[cc * 2], l[cc * 2]);
                split2h(av[cc].z, av[cc].w, h[cc * 2 + 1], l[cc * 2 + 1]);
            }
            u32 aoff = stb + (u32)(a_r * 80 + a_q * 32);
            asm volatile("st.shared.v4.b32 [%0], {%1,%2,%3,%4};" ::
                         "r"(aoff), "r"(h[0]), "r"(h[1]), "r"(h[2]), "r"(h[3]) : "memory");
            asm volatile("st.shared.v4.b32 [%0], {%1,%2,%3,%4};" ::
                         "r"(aoff + 16u), "r"(h[4]), "r"(h[5]), "r"(h[6]), "r"(h[7]) : "memory");
            asm volatile("st.shared.v4.b32 [%0], {%1,%2,%3,%4};" ::
                         "r"(aoff + 10240u), "r"(l[0]), "r"(l[1]), "r"(l[2]), "r"(l[3]) : "memory");
            asm volatile("st.shared.v4.b32 [%0], {%1,%2,%3,%4};" ::
                         "r"(aoff + 10256u), "r"(l[4]), "r"(l[5]), "r"(l[6]), "r"(l[7]) : "memory");
        }
        if (tid < 192) {
            u32 boff = stb + 20480u + (u32)(b_n * 80);
#pragma unroll
            for (int cc = 0; cc < 4; cc++)
                asm volatile("st.shared.v4.b32 [%0], {%1,%2,%3,%4};" ::
                             "r"(boff + (u32)cc * 16u),
                             "r"(bv[cc].x), "r"(bv[cc].y), "r"(bv[cc].z), "r"(bv[cc].w) : "memory");
        }
        // ---- prefetch stage ck+1 ----
        if (ck < 9) {
            const int kg = (ck + 1) * 32;
            const int kb = kg + a_q * 16;
#pragma unroll
            for (int cc = 0; cc < 4; cc++) {
                int k0 = kb + cc * 4;
                av[cc] = (tid < 256 && k0 < 300) ? *(const float4*)&X[(m0 + a_r) * 300 + k0]
                                                 : make_float4(0.f, 0.f, 0.f, 0.f);
            }
            if (tid < 192) {
#pragma unroll
                for (int cc = 0; cc < 4; cc++) {
                    int k0 = kg + cc * 8;
                    bv[cc] = (k0 < 304) ? *(const uint4*)&g_WtH[b_n * 304 + k0]
                                        : make_uint4(0u, 0u, 0u, 0u);
                }
            }
        }
        __syncthreads();
        // ---- compute: two k16 subtiles (one for the last stage) ----
        const int nkk = (ck < 9) ? 2 : 1;
        for (int kk = 0; kk < nkk; kk++) {
            const u32 ko = (u32)kk * 32u;
            u32 ah[2][4], al[2][4];
#pragma unroll
            for (int mf = 0; mf < 2; mf++) {
                u32 aaddr = stb + (u32)((warp_m * 32 + mf * 16 + l15) * 80) + ko + (u32)lkh16;
                ldsm4(ah[mf][0], ah[mf][1], ah[mf][2], ah[mf][3], aaddr);
                ldsm4(al[mf][0], al[mf][1], al[mf][2], al[mf][3], aaddr + 10240u);
            }
#pragma unroll
            for (int nf2 = 0; nf2 < 4; nf2++) {
                u32 baddr = stb + 20480u + (u32)((warp_n * 64 + nf2 * 16 + l15) * 80) + ko + (u32)lkh16;
                u32 bh0, bh1, bh2, bh3;
                ldsm4(bh0, bh1, bh2, bh3, baddr);
#pragma unroll
                for (int mf = 0; mf < 2; mf++) {
                    float* c0 = c[mf][nf2 * 2 + 0];
                    float* c1 = c[mf][nf2 * 2 + 1];
                    mma16816(c0, ah[mf][0], ah[mf][1], ah[mf][2], ah[mf][3], bh0, bh2);
                    mma16816(c0, al[mf][0], al[mf][1], al[mf][2], al[mf][3], bh0, bh2);
                    mma16816(c1, ah[mf][0], ah[mf][1], ah[mf][2], ah[mf][3], bh1, bh3);
                    mma16816(c1, al[mf][0], al[mf][1], al[mf][2], al[mf][3], bh1, bh3);
                }
            }
        }
    }

    // ---- epilogue: +bias, write g_pre ----
#pragma unroll
    for (int mf = 0; mf < 2; mf++) {
#pragma unroll
        for (int nf = 0; nf < 8; nf++) {
            int row = warp_m * 32 + mf * 16 + (lane >> 2);
            int col = warp_n * 64 + nf * 8 + 2 * (lane & 3);
            float bx = bias_s[col], by = bias_s[col + 1];
            float2 v0 = make_float2(c[mf][nf][0] + bx, c[mf][nf][1] + by);
            float2 v1 = make_float2(c[mf][nf][2] + bx, c[mf][nf][3] + by);
            *(float2*)&outp[(size_t)row * 192 + col] = v0;
            *(float2*)&outp[(size_t)(row + 8) * 192 + col] = v1;
        }
    }
}

// ---------------- sequential recurrence: 4 seqs/thread, dup-h, f32x2 ----------------
__global__ void __launch_bounds__(128) recur_kernel(const float* __restrict__ s) {
    __shared__ float2 W2s[64 * 64];                         // 32 KB
    __shared__ __align__(16) u64 hbuf[2][64][9];

    const int tid = threadIdx.x;
    const int j = tid & 63, grp = tid >> 6;

    for (int i = tid; i < 4096; i += 128) W2s[i] = g_hW2[i];

    const int ls0 = grp * 4;
    const int sbase = blockIdx.x * 8 + ls0;
    const float* __restrict__ pre[4];
#pragma unroll
    for (int i = 0; i < 4; i++) pre[i] = g_pre + (size_t)(sbase + i) * 24576u;

    const float h0 = tanhf(s[j]);
    const u64 h0d = pack2(h0, h0);
    float n[4], d[4], am[4], hf[4];
#pragma unroll
    for (int i = 0; i < 4; i++) {
        n[i] = 0.f; d[i] = 0.f; am[i] = -1e38f; hf[i] = h0;
        hbuf[0][j][ls0 + i] = h0d;
    }
    __syncthreads();
    int p = 0;

    float u[4], g[4], a[4];
#pragma unroll
    for (int i = 0; i < 4; i++) {
        u[i] = pre[i][j]; g[i] = pre[i][64 + j]; a[i] = pre[i][128 + j];
    }

    const int barid = grp + 1;

    for (int t = 0; t < 128; t++) {
        float nu[4], ng[4], na[4];
        if (t < 127) {
#pragma unroll
            for (int i = 0; i < 4; i++) {
                const float* q = pre[i] + (size_t)(t + 1) * 192;
                nu[i] = q[j]; ng[i] = q[64 + j]; na[i] = q[128 + j];
            }
        }

        u64 acc0 = pack2(g[0], a[0]), acc1 = pack2(g[1], a[1]);
        u64 acc2 = pack2(g[2], a[2]), acc3 = pack2(g[3], a[3]);
#pragma unroll
        for (int k = 0; k < 64; k++) {
            u64 w = *(const u64*)&W2s[k * 64 + j];
            const u64* hrow = &hbuf[p][k][ls0];
            acc0 = f32x2_fma(hrow[0], w, acc0);
            acc1 = f32x2_fma(hrow[1], w, acc1);
            acc2 = f32x2_fma(hrow[2], w, acc2);
            acc3 = f32x2_fma(hrow[3], w, acc3);
        }
        u64 accv[4] = {acc0, acc1, acc2, acc3};
#pragma unroll
        for (int i = 0; i < 4; i++) {
            float2 ga = unpack2(accv[i]);
            float z  = u[i] * tanhf(ga.x);
            float an = fmaxf(am[i], ga.y);
            float eo = __expf(am[i] - an);
            float ea = __expf(ga.y - an);
            n[i] = n[i] * eo + z * ea;
            d[i] = d[i] * eo + ea;
            am[i] = an;
            hf[i] = tanhf(n[i] / d[i]);
            hbuf[p ^ 1][j][ls0 + i] = pack2(hf[i], hf[i]);
        }
        asm volatile("bar.sync %0, 64;" :: "r"(barid) : "memory");
        p ^= 1;
#pragma unroll
        for (int i = 0; i < 4; i++) { u[i] = nu[i]; g[i] = ng[i]; a[i] = na[i]; }
    }

#pragma unroll
    for (int i = 0; i < 4; i++) {
        int sidx = sbase + i;
        g_hn[(sidx & 511) * 128 + (sidx >> 9) * 64 + j] = hf[i];
    }
}

// ---------------- batchnorm stats ----------------
__global__ void bnstats_kernel() {
    const int c = blockIdx.x;
    const int tid = threadIdx.x;
    float s = 0.f, sq = 0.f;
#pragma unroll
    for (int r = tid; r < 512; r += 256) {
        float v = g_hn[r * 128 + c];
        s += v; sq += v * v;
    }
#pragma unroll
    for (int o = 16; o; o >>= 1) {
        s  += __shfl_down_sync(0xffffffffu, s, o);
        sq += __shfl_down_sync(0xffffffffu, sq, o);
    }
    __shared__ float ss[8], qs[8];
    if ((tid & 31) == 0) { ss[tid >> 5] = s; qs[tid >> 5] = sq; }
    __syncthreads();
    if (tid == 0) {
        float S = 0.f, Q = 0.f;
#pragma unroll
        for (int w = 0; w < 8; w++) { S += ss[w]; Q += qs[w]; }
        float mean = S * (1.f / 512.f);
        float var  = Q * (1.f / 512.f) - mean * mean;
        g_bnm[c] = mean;
        g_bnr[c] = rsqrtf(var + 1e-5f);
    }
}

// ---------------- head ----------------
__global__ void head_kernel(const float* __restrict__ W1, const float* __restrict__ b1,
                            const float* __restrict__ pw, const float* __restrict__ W2,
                            const float* __restrict__ b2, float* __restrict__ out) {
    const int r = blockIdx.x;
    const int t = threadIdx.x;
    __shared__ float xs[128];
    for (int k = t; k < 128; k += 64)
        xs[k] = (g_hn[r * 128 + k] - g_bnm[k]) * g_bnr[k];
    __syncthreads();

    float acc = b1[t];
#pragma unroll
    for (int k = 0; k < 128; k++)
        acc = fmaf(xs[k], W1[k * 64 + t], acc);
    float pwv = *pw;
    acc = (acc >= 0.f) ? acc : pwv * acc;
    float v = acc * W2[t];
#pragma unroll
    for (int o = 16; o; o >>= 1) v += __shfl_down_sync(0xffffffffu, v, o);
    __shared__ float red[2];
    if ((t & 31) == 0) red[t >> 5] = v;
    __syncthreads();
    if (t == 0) {
        float sum = red[0] + red[1] + b2[0];
        out[r] = 1.f / (1.f + __expf(-sum));
    }
}

// ---------------- launch ----------------
extern "C" void kernel_launch(void* const* d_in, const int* in_sizes, int n_in,
                              void* d_out, int out_size) {
    const float* in1 = (const float*)d_in[0];
    const float* in2 = (const float*)d_in[1];
    const float* Wu  = (const float*)d_in[2];
    const float* bu  = (const float*)d_in[3];
    const float* Wg  = (const float*)d_in[4];
    const float* bg  = (const float*)d_in[5];
    const float* Wa  = (const float*)d_in[6];
    const float* s   = (const float*)d_in[7];
    const float* W1  = (const float*)d_in[8];
    const float* b1  = (const float*)d_in[9];
    const float* pw  = (const float*)d_in[10];
    const float* W2  = (const float*)d_in[11];
    const float* b2  = (const float*)d_in[12];
    float* out = (float*)d_out;

    cudaFuncSetAttribute(gemm_mma_kernel, cudaFuncAttributeMaxDynamicSharedMemorySize,
                         2 * STG_BYTES);

    pack_kernel<<<229, 256>>>(Wu, bu, Wg, bg, Wa);
    gemm_mma_kernel<<<dim3(512, 2), 384, 2 * STG_BYTES>>>(in1, in2);
    recur_kernel<<<128, 128>>>(s);
    bnstats_kernel<<<128, 256>>>();
    head_kernel<<<512, 64>>>(W1, b1, pw, W2, b2, out);
}

// round 13
// speedup vs baseline: 1.8850x; 1.1621x over previous
#include <cuda_runtime.h>
#include <cuda_fp16.h>

#define DI __device__ __forceinline__
typedef unsigned int u32;
typedef unsigned long long u64;

// B=512, T=128, D=300, H=64. M=65536 rows/input, 192 fused cols (u|g|a).
// GEMM: CTA = 128 rows x 192 cols, K 300->304, 10 k32 pipeline stages.
// Pure fp16 mma (Ah x Bh): combined rel err ~1.6e-4 (budget 1e-3).

// ---------------- device-global scratch ----------------
__device__ float          g_pre[2u * 65536u * 192u];   // [input][row][192]
__device__ unsigned short g_WtH[192 * 304];            // W^T fp16 [n][k], zero-pad k>=300
__device__ float          g_bias[192];                 // bu | bg | 0
__device__ float2         g_hW2[64 * 64];              // [k][j] = {Wg_h, Wa_h}
__device__ float          g_hn[512 * 128];
__device__ float          g_bnm[128];
__device__ float          g_bnr[128];

// ---------------- helpers ----------------
DI u64 f32x2_fma(u64 a, u64 b, u64 c) {
    u64 d;
    asm("fma.rn.f32x2 %0, %1, %2, %3;" : "=l"(d) : "l"(a), "l"(b), "l"(c));
    return d;
}
DI u64 pack2(float x, float y) {
    u64 r;
    asm("mov.b64 %0, {%1, %2};" : "=l"(r) : "f"(x), "f"(y));
    return r;
}
DI float2 unpack2(u64 v) {
    float2 f;
    asm("mov.b64 {%0, %1}, %2;" : "=f"(f.x), "=f"(f.y) : "l"(v));
    return f;
}
// pack two floats as fp16x2
DI u32 pack2h(float a, float b) {
    __half2 h = __floats2half2_rn(a, b);
    return *(u32*)&h;
}
DI void mma16816(float* c, u32 a0, u32 a1, u32 a2, u32 a3, u32 b0, u32 b1) {
    asm volatile(
        "mma.sync.aligned.m16n8k16.row.col.f32.f16.f16.f32 "
        "{%0,%1,%2,%3}, {%4,%5,%6,%7}, {%8,%9}, {%0,%1,%2,%3};"
        : "+f"(c[0]), "+f"(c[1]), "+f"(c[2]), "+f"(c[3])
        : "r"(a0), "r"(a1), "r"(a2), "r"(a3), "r"(b0), "r"(b1));
}
DI void ldsm4(u32& r0, u32& r1, u32& r2, u32& r3, u32 saddr) {
    asm volatile("ldmatrix.sync.aligned.m8n8.x4.shared.b16 {%0,%1,%2,%3}, [%4];"
                 : "=r"(r0), "=r"(r1), "=r"(r2), "=r"(r3) : "r"(saddr));
}
DI u32 smem_u32(const void* p) {
    u32 a;
    asm("{ .reg .u64 t; cvta.to.shared.u64 t, %1; cvt.u32.u64 %0, t; }" : "=r"(a) : "l"(p));
    return a;
}

// ---------------- weight packing ----------------
__global__ void pack_kernel(const float* __restrict__ Wu, const float* __restrict__ bu,
                            const float* __restrict__ Wg, const float* __restrict__ bg,
                            const float* __restrict__ Wa) {
    int i = blockIdx.x * blockDim.x + threadIdx.x;
    if (i < 192 * 304) {
        int n = i / 304, k = i % 304;
        float v = 0.f;
        if (k < 300) {
            if (n < 64)       v = Wu[k * 64 + n];
            else if (n < 128) v = Wg[k * 64 + (n - 64)];
            else              v = Wa[k * 64 + (n - 128)];
        }
        g_WtH[i] = __half_as_ushort(__float2half_rn(v));
    }
    if (i < 192) g_bias[i] = (i < 64) ? bu[i] : (i < 128 ? bg[i - 64] : 0.f);
    if (i < 64 * 64) {
        int k = i / 64, j = i % 64;
        g_hW2[i] = make_float2(Wg[(300 + k) * 64 + j], Wa[(300 + k) * 64 + j]);
    }
}

// ---------------- full-N fp16 mma GEMM, k32 stages: pre = x @ Wcat + bias ----------------
// grid (512, 2); 384 threads = 12 warps (4m x 3n), warp tile 32x64.
// Stage (25600 B): AH 0 (128x80B), BH 10240 (192x80B). 2 stages.
// Row stride 80 B => 8 consecutive rows hit 8 distinct 16B bank-groups (conflict-free LDSM).
#define STG_BYTES 25600u
__global__ void __launch_bounds__(384) gemm_mma_kernel(const float* __restrict__ x1,
                                                       const float* __restrict__ x2) {
    extern __shared__ __align__(16) unsigned short dyns[];
    __shared__ float bias_s[192];

    const int tid = threadIdx.x, lane = tid & 31, wid = tid >> 5;
    const int warp_m = wid & 3, warp_n = wid >> 2;
    const int mblk = blockIdx.x, inp = blockIdx.y;
    const float* __restrict__ X = inp ? x2 : x1;
    const size_t m0 = (size_t)mblk * 128u;
    float* __restrict__ outp = g_pre + ((size_t)inp * 65536u + m0) * 192u;

    if (tid < 192) bias_s[tid] = g_bias[tid];

    const u32 sb = smem_u32(dyns);

    // loader maps
    const int a_r = tid >> 1, a_q = tid & 1;          // A: threads 0..255, 16 k each
    const int b_n = tid;                              // B: threads 0..191, full k32 row

    float c[2][8][4];
#pragma unroll
    for (int i = 0; i < 2; i++)
#pragma unroll
        for (int j = 0; j < 8; j++)
#pragma unroll
            for (int q = 0; q < 4; q++) c[i][j][q] = 0.f;

    // prefetch stage 0
    float4 av[4];
    uint4 bv[4];
    {
        const int kb = a_q * 16;
#pragma unroll
        for (int cc = 0; cc < 4; cc++) {
            int k0 = kb + cc * 4;
            av[cc] = (tid < 256 && k0 < 300) ? *(const float4*)&X[(m0 + a_r) * 300 + k0]
                                             : make_float4(0.f, 0.f, 0.f, 0.f);
        }
        if (tid < 192) {
#pragma unroll
            for (int cc = 0; cc < 4; cc++)
                bv[cc] = *(const uint4*)&g_WtH[b_n * 304 + cc * 8];
        }
    }

    const int l15 = lane & 15, lkh16 = (lane >> 4) * 16;   // byte offset of k-half

    for (int ck = 0; ck < 10; ck++) {
        const u32 stb = sb + (u32)(ck & 1) * STG_BYTES;
        // ---- STS stage ----
        if (tid < 256) {
            u32 h[8];
#pragma unroll
            for (int cc = 0; cc < 4; cc++) {
                h[cc * 2]     = pack2h(av[cc].x, av[cc].y);
                h[cc * 2 + 1] = pack2h(av[cc].z, av[cc].w);
            }
            u32 aoff = stb + (u32)(a_r * 80 + a_q * 32);
            asm volatile("st.shared.v4.b32 [%0], {%1,%2,%3,%4};" ::
                         "r"(aoff), "r"(h[0]), "r"(h[1]), "r"(h[2]), "r"(h[3]) : "memory");
            asm volatile("st.shared.v4.b32 [%0], {%1,%2,%3,%4};" ::
                         "r"(aoff + 16u), "r"(h[4]), "r"(h[5]), "r"(h[6]), "r"(h[7]) : "memory");
        }
        if (tid < 192) {
            u32 boff = stb + 10240u + (u32)(b_n * 80);
#pragma unroll
            for (int cc = 0; cc < 4; cc++)
                asm volatile("st.shared.v4.b32 [%0], {%1,%2,%3,%4};" ::
                             "r"(boff + (u32)cc * 16u),
                             "r"(bv[cc].x), "r"(bv[cc].y), "r"(bv[cc].z), "r"(bv[cc].w) : "memory");
        }
        // ---- prefetch stage ck+1 ----
        if (ck < 9) {
            const int kg = (ck + 1) * 32;
            const int kb = kg + a_q * 16;
#pragma unroll
            for (int cc = 0; cc < 4; cc++) {
                int k0 = kb + cc * 4;
                av[cc] = (tid < 256 && k0 < 300) ? *(const float4*)&X[(m0 + a_r) * 300 + k0]
                                                 : make_float4(0.f, 0.f, 0.f, 0.f);
            }
            if (tid < 192) {
#pragma unroll
                for (int cc = 0; cc < 4; cc++) {
                    int k0 = kg + cc * 8;
                    bv[cc] = (k0 < 304) ? *(const uint4*)&g_WtH[b_n * 304 + k0]
                                        : make_uint4(0u, 0u, 0u, 0u);
                }
            }
        }
        __syncthreads();
        // ---- compute: two k16 subtiles (one for the last stage) ----
        const int nkk = (ck < 9) ? 2 : 1;
        for (int kk = 0; kk < nkk; kk++) {
            const u32 ko = (u32)kk * 32u;
            u32 ah[2][4];
#pragma unroll
            for (int mf = 0; mf < 2; mf++) {
                u32 aaddr = stb + (u32)((warp_m * 32 + mf * 16 + l15) * 80) + ko + (u32)lkh16;
                ldsm4(ah[mf][0], ah[mf][1], ah[mf][2], ah[mf][3], aaddr);
            }
#pragma unroll
            for (int nf2 = 0; nf2 < 4; nf2++) {
                u32 baddr = stb + 10240u + (u32)((warp_n * 64 + nf2 * 16 + l15) * 80) + ko + (u32)lkh16;
                u32 bh0, bh1, bh2, bh3;
                ldsm4(bh0, bh1, bh2, bh3, baddr);
#pragma unroll
                for (int mf = 0; mf < 2; mf++) {
                    mma16816(c[mf][nf2 * 2 + 0], ah[mf][0], ah[mf][1], ah[mf][2], ah[mf][3], bh0, bh2);
                    mma16816(c[mf][nf2 * 2 + 1], ah[mf][0], ah[mf][1], ah[mf][2], ah[mf][3], bh1, bh3);
                }
            }
        }
    }

    // ---- epilogue: +bias, write g_pre ----
#pragma unroll
    for (int mf = 0; mf < 2; mf++) {
#pragma unroll
        for (int nf = 0; nf < 8; nf++) {
            int row = warp_m * 32 + mf * 16 + (lane >> 2);
            int col = warp_n * 64 + nf * 8 + 2 * (lane & 3);
            float bx = bias_s[col], by = bias_s[col + 1];
            float2 v0 = make_float2(c[mf][nf][0] + bx, c[mf][nf][1] + by);
            float2 v1 = make_float2(c[mf][nf][2] + bx, c[mf][nf][3] + by);
            *(float2*)&outp[(size_t)row * 192 + col] = v0;
            *(float2*)&outp[(size_t)(row + 8) * 192 + col] = v1;
        }
    }
}

// ---------------- sequential recurrence: 4 seqs/thread, dup-h, f32x2 ----------------
__global__ void __launch_bounds__(128) recur_kernel(const float* __restrict__ s) {
    __shared__ float2 W2s[64 * 64];                         // 32 KB
    __shared__ __align__(16) u64 hbuf[2][64][9];

    const int tid = threadIdx.x;
    const int j = tid & 63, grp = tid >> 6;

    for (int i = tid; i < 4096; i += 128) W2s[i] = g_hW2[i];

    const int ls0 = grp * 4;
    const int sbase = blockIdx.x * 8 + ls0;
    const float* __restrict__ pre[4];
#pragma unroll
    for (int i = 0; i < 4; i++) pre[i] = g_pre + (size_t)(sbase + i) * 24576u;

    const float h0 = tanhf(s[j]);
    const u64 h0d = pack2(h0, h0);
    float n[4], d[4], am[4], hf[4];
#pragma unroll
    for (int i = 0; i < 4; i++) {
        n[i] = 0.f; d[i] = 0.f; am[i] = -1e38f; hf[i] = h0;
        hbuf[0][j][ls0 + i] = h0d;
    }
    __syncthreads();
    int p = 0;

    float u[4], g[4], a[4];
#pragma unroll
    for (int i = 0; i < 4; i++) {
        u[i] = pre[i][j]; g[i] = pre[i][64 + j]; a[i] = pre[i][128 + j];
    }

    const int barid = grp + 1;

    for (int t = 0; t < 128; t++) {
        float nu[4], ng[4], na[4];
        if (t < 127) {
#pragma unroll
            for (int i = 0; i < 4; i++) {
                const float* q = pre[i] + (size_t)(t + 1) * 192;
                nu[i] = q[j]; ng[i] = q[64 + j]; na[i] = q[128 + j];
            }
        }

        u64 acc0 = pack2(g[0], a[0]), acc1 = pack2(g[1], a[1]);
        u64 acc2 = pack2(g[2], a[2]), acc3 = pack2(g[3], a[3]);
#pragma unroll
        for (int k = 0; k < 64; k++) {
            u64 w = *(const u64*)&W2s[k * 64 + j];
            const u64* hrow = &hbuf[p][k][ls0];
            acc0 = f32x2_fma(hrow[0], w, acc0);
            acc1 = f32x2_fma(hrow[1], w, acc1);
            acc2 = f32x2_fma(hrow[2], w, acc2);
            acc3 = f32x2_fma(hrow[3], w, acc3);
        }
        u64 accv[4] = {acc0, acc1, acc2, acc3};
#pragma unroll
        for (int i = 0; i < 4; i++) {
            float2 ga = unpack2(accv[i]);
            float z  = u[i] * tanhf(ga.x);
            float an = fmaxf(am[i], ga.y);
            float eo = __expf(am[i] - an);
            float ea = __expf(ga.y - an);
            n[i] = n[i] * eo + z * ea;
            d[i] = d[i] * eo + ea;
            am[i] = an;
            hf[i] = tanhf(n[i] / d[i]);
            hbuf[p ^ 1][j][ls0 + i] = pack2(hf[i], hf[i]);
        }
        asm volatile("bar.sync %0, 64;" :: "r"(barid) : "memory");
        p ^= 1;
#pragma unroll
        for (int i = 0; i < 4; i++) { u[i] = nu[i]; g[i] = ng[i]; a[i] = na[i]; }
    }

#pragma unroll
    for (int i = 0; i < 4; i++) {
        int sidx = sbase + i;
        g_hn[(sidx & 511) * 128 + (sidx >> 9) * 64 + j] = hf[i];
    }
}

// ---------------- batchnorm stats ----------------
__global__ void bnstats_kernel() {
    const int c = blockIdx.x;
    const int tid = threadIdx.x;
    float s = 0.f, sq = 0.f;
#pragma unroll
    for (int r = tid; r < 512; r += 256) {
        float v = g_hn[r * 128 + c];
        s += v; sq += v * v;
    }
#pragma unroll
    for (int o = 16; o; o >>= 1) {
        s  += __shfl_down_sync(0xffffffffu, s, o);
        sq += __shfl_down_sync(0xffffffffu, sq, o);
    }
    __shared__ float ss[8], qs[8];
    if ((tid & 31) == 0) { ss[tid >> 5] = s; qs[tid >> 5] = sq; }
    __syncthreads();
    if (tid == 0) {
        float S = 0.f, Q = 0.f;
#pragma unroll
        for (int w = 0; w < 8; w++) { S += ss[w]; Q += qs[w]; }
        float mean = S * (1.f / 512.f);
        float var  = Q * (1.f / 512.f) - mean * mean;
        g_bnm[c] = mean;
        g_bnr[c] = rsqrtf(var + 1e-5f);
    }
}

// ---------------- head ----------------
__global__ void head_kernel(const float* __restrict__ W1, const float* __restrict__ b1,
                            const float* __restrict__ pw, const float* __restrict__ W2,
                            const float* __restrict__ b2, float* __restrict__ out) {
    const int r = blockIdx.x;
    const int t = threadIdx.x;
    __shared__ float xs[128];
    for (int k = t; k < 128; k += 64)
        xs[k] = (g_hn[r * 128 + k] - g_bnm[k]) * g_bnr[k];
    __syncthreads();

    float acc = b1[t];
#pragma unroll
    for (int k = 0; k < 128; k++)
        acc = fmaf(xs[k], W1[k * 64 + t], acc);
    float pwv = *pw;
    acc = (acc >= 0.f) ? acc : pwv * acc;
    float v = acc * W2[t];
#pragma unroll
    for (int o = 16; o; o >>= 1) v += __shfl_down_sync(0xffffffffu, v, o);
    __shared__ float red[2];
    if ((t & 31) == 0) red[t >> 5] = v;
    __syncthreads();
    if (t == 0) {
        float sum = red[0] + red[1] + b2[0];
        out[r] = 1.f / (1.f + __expf(-sum));
    }
}

// ---------------- launch ----------------
extern "C" void kernel_launch(void* const* d_in, const int* in_sizes, int n_in,
                              void* d_out, int out_size) {
    const float* in1 = (const float*)d_in[0];
    const float* in2 = (const float*)d_in[1];
    const float* Wu  = (const float*)d_in[2];
    const float* bu  = (const float*)d_in[3];
    const float* Wg  = (const float*)d_in[4];
    const float* bg  = (const float*)d_in[5];
    const float* Wa  = (const float*)d_in[6];
    const float* s   = (const float*)d_in[7];
    const float* W1  = (const float*)d_in[8];
    const float* b1  = (const float*)d_in[9];
    const float* pw  = (const float*)d_in[10];
    const float* W2  = (const float*)d_in[11];
    const float* b2  = (const float*)d_in[12];
    float* out = (float*)d_out;

    cudaFuncSetAttribute(gemm_mma_kernel, cudaFuncAttributeMaxDynamicSharedMemorySize,
                         2 * STG_BYTES);

    pack_kernel<<<229, 256>>>(Wu, bu, Wg, bg, Wa);
    gemm_mma_kernel<<<dim3(512, 2), 384, 2 * STG_BYTES>>>(in1, in2);
    recur_kernel<<<128, 128>>>(s);
    bnstats_kernel<<<128, 256>>>();
    head_kernel<<<512, 64>>>(W1, b1, pw, W2, b2, out);
}